// round 12
// baseline (speedup 1.0000x reference)
#include <cuda_runtime.h>
#include <cuda_bf16.h>
#include <cstdint>
#include <math.h>

#define NB 8
#define NC 512
#define ND 256
#define NT 2048

typedef __nv_bfloat16 bf16;

// ---------------- scratch (device globals; no allocations allowed) ----------
__device__ float g_W [(size_t)NB * NT * NT];     // W / P fp32 (B,T,S)
__device__ float g_h [(size_t)NB * NC * NT];     // h fp32 (B,C,T)
// bf16 hi/lo planes
__device__ bf16 g_thTh[(size_t)NB * NT * ND], g_thTl[(size_t)NB * NT * ND]; // theta^T (T,D)
__device__ bf16 g_phTh[(size_t)NB * NT * ND], g_phTl[(size_t)NB * NT * ND]; // phi^T   (T,D)
__device__ bf16 g_gh  [(size_t)NB * ND * NT], g_gl  [(size_t)NB * ND * NT]; // g       (D,T)
__device__ bf16 g_atTh[(size_t)NB * NT * ND], g_atTl[(size_t)NB * NT * ND]; // attn^T  (S,D)
__device__ bf16 g_inh [(size_t)NB * NC * NT], g_inl [(size_t)NB * NC * NT]; // inpt    (C,T)
__device__ bf16 g_twh [ND * NC], g_twl [ND * NC];
__device__ bf16 g_pwh [ND * NC], g_pwl [ND * NC];
__device__ bf16 g_gwh [ND * NC], g_gwl [ND * NC];
__device__ bf16 g_hwh [NC * ND], g_hwl [NC * ND];
__device__ float g_mean[NC];
__device__ float g_istd[NC];

// ---------------- helpers ----------------------------------------------------
__device__ __forceinline__ void split2(float x, float y, uint32_t& hi, uint32_t& lo) {
    __nv_bfloat162 h = __floats2bfloat162_rn(x, y);
    float hx = __low2float(h), hy = __high2float(h);
    __nv_bfloat162 l = __floats2bfloat162_rn(x - hx, y - hy);
    hi = *reinterpret_cast<uint32_t*>(&h);
    lo = *reinterpret_cast<uint32_t*>(&l);
}

__device__ __forceinline__ void mma16(float* d, const uint32_t* a, const uint32_t* b) {
    asm volatile(
        "mma.sync.aligned.m16n8k16.row.col.f32.bf16.bf16.f32 "
        "{%0,%1,%2,%3}, {%4,%5,%6,%7}, {%8,%9}, {%0,%1,%2,%3};"
        : "+f"(d[0]), "+f"(d[1]), "+f"(d[2]), "+f"(d[3])
        : "r"(a[0]), "r"(a[1]), "r"(a[2]), "r"(a[3]), "r"(b[0]), "r"(b[1]));
}

// SMEM geometry (fragment-permuted, bf16 pair-packed uint32 words)
#define A_PLANE 2112            // 16*132 words
#define B_PLANE 2176            // 32*68 words
#define BUF_WORDS (2*A_PLANE + 2*B_PLANE)   // 8576 (Ahi, Alo, Bhi, Blo)
#define NSTAGE 3
static constexpr int SMEM_BYTES = NSTAGE * BUF_WORDS * 4;   // 102912

// ---------------- bf16x3 GEMM, pre-split operands, 3-stage pipeline ----------
// A ALWAYS bf16 planes, natural (M,K) row-major (lda).
// TB=false: B natural (N,K). TB=true: B is (K,N).
// BSPL: B is bf16 planes; else B is fp32 (split2 at STS time).
// OSPL: C written as bf16 hi/lo planes; else fp32.
// TOUT: C[n*ldc+m] else C[m*ldc+n]. Bias per-m (fp32).
// FUSED3: blockIdx.z = op*NB + b; op<2 TOUT planes (ldc=ND), op==2 natural planes (ldc=NT).
template <bool TB, bool TOUT, bool BIAS, bool FUSED3, bool BSPL, bool OSPL>
__global__ __launch_bounds__(256, 2) void tgemm(
    const bf16* __restrict__ Ahi, const bf16* __restrict__ Alo,
    const void* __restrict__ Bp,  const void* __restrict__ Bp2,
    void* __restrict__ Cp, void* __restrict__ Cp2,
    const float* __restrict__ bias,
    const bf16* A1hi, const bf16* A1lo, void* C1p, void* C1p2, const float* bias1,
    const bf16* A2hi, const bf16* A2lo, void* C2p, void* C2p2, const float* bias2,
    int K, int lda, int ldb, int ldc,
    long long sA, long long sB, long long sC)
{
    extern __shared__ uint32_t sm[];
    const int tid = threadIdx.x;
    const int lane = tid & 31;
    const int wid = tid >> 5;
    const int warpM = wid >> 2, warpN = wid & 3;   // 2 x 4 warp grid
    const int g4 = lane >> 2, tig = lane & 3;

    int bz = blockIdx.z;
    int opsel = 0;
    if (FUSED3) {
        opsel = bz >> 3;       // 0:theta 1:phi 2:g
        bz &= 7;
        if (opsel == 1) { Ahi = A1hi; Alo = A1lo; Cp = C1p; Cp2 = C1p2; bias = bias1; }
        else if (opsel == 2) { Ahi = A2hi; Alo = A2lo; Cp = C2p; Cp2 = C2p2; bias = bias2; ldc = NT; }
    }
    const int m0 = blockIdx.y * 128, n0 = blockIdx.x * 128;
    Ahi += (long long)bz * sA;  Alo += (long long)bz * sA;
    const bf16*  Bh_g = BSPL ? (const bf16*)Bp  + (long long)bz * sB : nullptr;
    const bf16*  Bl_g = BSPL ? (const bf16*)Bp2 + (long long)bz * sB : nullptr;
    const float* Bf_g = BSPL ? nullptr : (const float*)Bp + (long long)bz * sB;
    bf16*  Chg = OSPL ? (bf16*)Cp  + (long long)bz * sC : nullptr;
    bf16*  Clg = OSPL ? (bf16*)Cp2 + (long long)bz * sC : nullptr;
    float* Cfg = OSPL ? nullptr : (float*)Cp + (long long)bz * sC;

    const int w_row = tid >> 3;       // 0..31
    const int w_q   = tid & 7;        // k-quad index

    float acc[4][4][4];
#pragma unroll
    for (int a = 0; a < 4; a++)
#pragma unroll
        for (int b = 0; b < 4; b++)
#pragma unroll
            for (int c = 0; c < 4; c++) acc[a][b][c] = 0.f;

    const int nch = K >> 5;
    uint2 pah[4], pal[4];              // A planes: 4 rows x (4 bf16 hi + 4 bf16 lo)
    uint2 pbh[4], pbl[4];              // B natural planes
    uint32_t pth[4][2], ptl[4][2];     // B TB planes (packed pairs)
    float pbt[16];                     // B TB fp32

    // ---- global loads into registers ----
    auto ldgA = [&](int ch) {
        const bf16* ph = Ahi + (size_t)m0 * lda + ch * 32 + w_q * 4;
        const bf16* pl = Alo + (size_t)m0 * lda + ch * 32 + w_q * 4;
#pragma unroll
        for (int i = 0; i < 4; i++) {
            pah[i] = *(const uint2*)(ph + (size_t)(w_row + i * 32) * lda);
            pal[i] = *(const uint2*)(pl + (size_t)(w_row + i * 32) * lda);
        }
    };
    auto ldgB = [&](int ch) {
        if (TB) {
            const int n = tid & 127, kq0 = tid >> 7;
            if (BSPL) {
                const unsigned short* bh = (const unsigned short*)(Bh_g + (size_t)(ch * 32) * ldb + n0 + n);
                const unsigned short* bl = (const unsigned short*)(Bl_g + (size_t)(ch * 32) * ldb + n0 + n);
#pragma unroll
                for (int i = 0; i < 4; i++) {
                    const size_t r0 = (size_t)((kq0 + 2 * i) * 4) * ldb;
                    unsigned short h0 = bh[r0], h1 = bh[r0 + ldb], h2 = bh[r0 + 2 * (size_t)ldb], h3 = bh[r0 + 3 * (size_t)ldb];
                    unsigned short l0 = bl[r0], l1 = bl[r0 + ldb], l2 = bl[r0 + 2 * (size_t)ldb], l3 = bl[r0 + 3 * (size_t)ldb];
                    pth[i][0] = (uint32_t)h0 | ((uint32_t)h1 << 16);
                    pth[i][1] = (uint32_t)h2 | ((uint32_t)h3 << 16);
                    ptl[i][0] = (uint32_t)l0 | ((uint32_t)l1 << 16);
                    ptl[i][1] = (uint32_t)l2 | ((uint32_t)l3 << 16);
                }
            } else {
                const float* Bg = Bf_g + (size_t)(ch * 32) * ldb + n0 + n;
#pragma unroll
                for (int i = 0; i < 4; i++) {
                    const float* p = Bg + (size_t)((kq0 + 2 * i) * 4) * ldb;
                    pbt[i * 4 + 0] = p[0];
                    pbt[i * 4 + 1] = p[(size_t)ldb];
                    pbt[i * 4 + 2] = p[2 * (size_t)ldb];
                    pbt[i * 4 + 3] = p[3 * (size_t)ldb];
                }
            }
        } else {
            const bf16* ph = Bh_g + (size_t)n0 * ldb + ch * 32 + w_q * 4;
            const bf16* pl = Bl_g + (size_t)n0 * ldb + ch * 32 + w_q * 4;
#pragma unroll
            for (int i = 0; i < 4; i++) {
                pbh[i] = *(const uint2*)(ph + (size_t)(w_row + i * 32) * ldb);
                pbl[i] = *(const uint2*)(pl + (size_t)(w_row + i * 32) * ldb);
            }
        }
    };

    // ---- registers -> split bf16 planes in permuted SMEM ----
    auto stsTile = [&](int buf) {
        uint32_t* Ah = sm + buf * BUF_WORDS;
        uint32_t* Al = Ah + A_PLANE;
        uint32_t* Bh = Ah + 2 * A_PLANE;
        uint32_t* Bl = Bh + B_PLANE;
#pragma unroll
        for (int i = 0; i < 4; i++) {
            const int row = w_row + i * 32;
            const int mf = row >> 4, rm = row & 15, ks = w_q >> 2;
            const int p0 = (2 * w_q) & 7, half = p0 >> 2, pl = p0 & 3;
            const int rg = half * 2 + (rm >> 3);
            const int w0 = (mf * 2 + ks) * 132 + ((rm & 7) * 4 + pl) * 4 + rg;
            Ah[w0] = pah[i].x; Ah[w0 + 4] = pah[i].y;
            Al[w0] = pal[i].x; Al[w0 + 4] = pal[i].y;
        }
        if (TB) {
            const int n = tid & 127, kq0 = tid >> 7;
            const int nf = n >> 3, g = n & 7;
#pragma unroll
            for (int i = 0; i < 4; i++) {
                const int q = kq0 + 2 * i;
                const int ks = q >> 2, p0 = (2 * q) & 7, half = p0 >> 2, pl = p0 & 3;
                const int w0 = (nf * 2 + ks) * 68 + (g * 4 + pl) * 2 + half;
                if (BSPL) {
                    Bh[w0] = pth[i][0]; Bh[w0 + 2] = pth[i][1];
                    Bl[w0] = ptl[i][0]; Bl[w0 + 2] = ptl[i][1];
                } else {
                    uint32_t h0, l0, h1, l1;
                    split2(pbt[i * 4 + 0], pbt[i * 4 + 1], h0, l0);
                    split2(pbt[i * 4 + 2], pbt[i * 4 + 3], h1, l1);
                    Bh[w0] = h0; Bh[w0 + 2] = h1;
                    Bl[w0] = l0; Bl[w0 + 2] = l1;
                }
            }
        } else {
#pragma unroll
            for (int i = 0; i < 4; i++) {
                const int n = w_row + i * 32;
                const int nf = n >> 3, g = n & 7, ks = w_q >> 2;
                const int p0 = (2 * w_q) & 7, half = p0 >> 2, pl = p0 & 3;
                const int w0 = (nf * 2 + ks) * 68 + (g * 4 + pl) * 2 + half;
                Bh[w0] = pbh[i].x; Bh[w0 + 2] = pbh[i].y;
                Bl[w0] = pbl[i].x; Bl[w0 + 2] = pbl[i].y;
            }
        }
    };

    // ---- compute one 32-k chunk: hi*hi + lo*hi + hi*lo ----
    auto compute = [&](int buf) {
        const uint32_t* Ah = sm + buf * BUF_WORDS;
        const uint32_t* Al = Ah + A_PLANE;
        const uint32_t* Bh = Ah + 2 * A_PLANE;
        const uint32_t* Bl = Bh + B_PLANE;
#pragma unroll
        for (int ks = 0; ks < 2; ks++) {
            uint32_t afh[4][4], bfh[4][2];
#pragma unroll
            for (int mf = 0; mf < 4; mf++)
                *(uint4*)afh[mf] = *(const uint4*)(Ah + ((warpM * 4 + mf) * 2 + ks) * 132 + lane * 4);
#pragma unroll
            for (int nf = 0; nf < 4; nf++)
                *(uint2*)bfh[nf] = *(const uint2*)(Bh + ((warpN * 4 + nf) * 2 + ks) * 68 + lane * 2);
#pragma unroll
            for (int mf = 0; mf < 4; mf++)
#pragma unroll
                for (int nf = 0; nf < 4; nf++)
                    mma16(acc[mf][nf], afh[mf], bfh[nf]);
#pragma unroll
            for (int mf = 0; mf < 4; mf++) {
                uint32_t t[4];
                *(uint4*)t = *(const uint4*)(Al + ((warpM * 4 + mf) * 2 + ks) * 132 + lane * 4);
#pragma unroll
                for (int nf = 0; nf < 4; nf++)
                    mma16(acc[mf][nf], t, bfh[nf]);
            }
#pragma unroll
            for (int nf = 0; nf < 4; nf++) {
                uint32_t t[2];
                *(uint2*)t = *(const uint2*)(Bl + ((warpN * 4 + nf) * 2 + ks) * 68 + lane * 2);
#pragma unroll
                for (int mf = 0; mf < 4; mf++)
                    mma16(acc[mf][nf], afh[mf], t);
            }
        }
    };

    // ---- 3-stage pipelined loop, prefetch distance 2, ONE barrier per chunk --
    int b_sts = 1, b_cmp = 0;
    ldgA(0); ldgB(0);
    stsTile(0);
    if (nch > 1) { ldgA(1); ldgB(1); }
    __syncthreads();
    for (int ch = 0; ch < nch; ch++) {
        if (ch + 1 < nch) {
            stsTile(b_sts);
            if (++b_sts == NSTAGE) b_sts = 0;
            if (ch + 2 < nch) { ldgA(ch + 2); ldgB(ch + 2); }
        }
        compute(b_cmp);
        if (++b_cmp == NSTAGE) b_cmp = 0;
        if (ch + 1 < nch) __syncthreads();
    }

    // ---- epilogue ----
    const bool toutR = FUSED3 ? (opsel < 2) : TOUT;
#pragma unroll
    for (int mf = 0; mf < 4; mf++) {
        const int m = m0 + warpM * 64 + mf * 16 + g4;
        const float bv0 = BIAS ? bias[m] : 0.f;
        const float bv1 = BIAS ? bias[m + 8] : 0.f;
#pragma unroll
        for (int nf = 0; nf < 4; nf++) {
            const int n = n0 + warpN * 32 + nf * 8 + 2 * tig;
            const float v0 = acc[mf][nf][0] + bv0, v1 = acc[mf][nf][1] + bv0;
            const float v2 = acc[mf][nf][2] + bv1, v3 = acc[mf][nf][3] + bv1;
            if (toutR) {
                if (OSPL) {
                    bf16 h;
                    h = __float2bfloat16_rn(v0); Chg[(size_t)n * ldc + m] = h;
                    Clg[(size_t)n * ldc + m] = __float2bfloat16_rn(v0 - __bfloat162float(h));
                    h = __float2bfloat16_rn(v1); Chg[(size_t)(n + 1) * ldc + m] = h;
                    Clg[(size_t)(n + 1) * ldc + m] = __float2bfloat16_rn(v1 - __bfloat162float(h));
                    h = __float2bfloat16_rn(v2); Chg[(size_t)n * ldc + m + 8] = h;
                    Clg[(size_t)n * ldc + m + 8] = __float2bfloat16_rn(v2 - __bfloat162float(h));
                    h = __float2bfloat16_rn(v3); Chg[(size_t)(n + 1) * ldc + m + 8] = h;
                    Clg[(size_t)(n + 1) * ldc + m + 8] = __float2bfloat16_rn(v3 - __bfloat162float(h));
                } else {
                    Cfg[(size_t)n * ldc + m]           = v0;
                    Cfg[(size_t)(n + 1) * ldc + m]     = v1;
                    Cfg[(size_t)n * ldc + m + 8]       = v2;
                    Cfg[(size_t)(n + 1) * ldc + m + 8] = v3;
                }
            } else {
                if (OSPL) {
                    uint32_t h01, l01, h23, l23;
                    split2(v0, v1, h01, l01);
                    split2(v2, v3, h23, l23);
                    *(uint32_t*)((unsigned short*)Chg + (size_t)m * ldc + n) = h01;
                    *(uint32_t*)((unsigned short*)Clg + (size_t)m * ldc + n) = l01;
                    *(uint32_t*)((unsigned short*)Chg + (size_t)(m + 8) * ldc + n) = h23;
                    *(uint32_t*)((unsigned short*)Clg + (size_t)(m + 8) * ldc + n) = l23;
                } else {
                    *(float2*)(Cfg + (size_t)m * ldc + n)       = make_float2(v0, v1);
                    *(float2*)(Cfg + (size_t)(m + 8) * ldc + n) = make_float2(v2, v3);
                }
            }
        }
    }
}

// ---------------- fp32 -> bf16 hi/lo plane split ------------------------------
__global__ __launch_bounds__(256) void split_kernel(
    const float4* __restrict__ src, uint2* __restrict__ hi, uint2* __restrict__ lo, int n4)
{
    const int i = blockIdx.x * 256 + threadIdx.x;
    if (i >= n4) return;
    const float4 v = src[i];
    uint32_t h0, l0, h1, l1;
    split2(v.x, v.y, h0, l0);
    split2(v.z, v.w, h1, l1);
    hi[i] = make_uint2(h0, h1);
    lo[i] = make_uint2(l0, l1);
}

// ---------------- softmax (in place over rows of W), float4 ------------------
__global__ __launch_bounds__(256) void softmax_kernel(float* __restrict__ W)
{
    float4* p4 = (float4*)(W + (size_t)blockIdx.x * NT);
    const int t = threadIdx.x;
    float4 a = p4[t], b = p4[t + 256];
    float x[8] = {a.x, a.y, a.z, a.w, b.x, b.y, b.z, b.w};

    float m = x[0];
#pragma unroll
    for (int r = 1; r < 8; r++) m = fmaxf(m, x[r]);
#pragma unroll
    for (int o = 16; o; o >>= 1) m = fmaxf(m, __shfl_xor_sync(0xffffffffu, m, o));
    __shared__ float smax[8], ssum[8];
    if ((t & 31) == 0) smax[t >> 5] = m;
    __syncthreads();
    m = smax[0];
#pragma unroll
    for (int i = 1; i < 8; i++) m = fmaxf(m, smax[i]);
    float e[8], s = 0.f;
#pragma unroll
    for (int r = 0; r < 8; r++) { e[r] = __expf(x[r] - m); s += e[r]; }
#pragma unroll
    for (int o = 16; o; o >>= 1) s += __shfl_xor_sync(0xffffffffu, s, o);
    if ((t & 31) == 0) ssum[t >> 5] = s;
    __syncthreads();
    s = ssum[0];
#pragma unroll
    for (int i = 1; i < 8; i++) s += ssum[i];
    const float inv = 1.f / s;
    p4[t]       = make_float4(e[0] * inv, e[1] * inv, e[2] * inv, e[3] * inv);
    p4[t + 256] = make_float4(e[4] * inv, e[5] * inv, e[6] * inv, e[7] * inv);
}

// ---------------- BatchNorm stats + apply ------------------------------------
__global__ __launch_bounds__(256) void bn_stats_kernel(
    const float* __restrict__ h, float* __restrict__ mean, float* __restrict__ istd)
{
    const int c = blockIdx.x;
    float s1 = 0.f, s2 = 0.f;
    for (int i = threadIdx.x; i < NB * NT; i += 256) {
        const int b = i >> 11, t = i & (NT - 1);
        const float v = h[(size_t)b * NC * NT + (size_t)c * NT + t];
        s1 += v; s2 += v * v;
    }
#pragma unroll
    for (int o = 16; o; o >>= 1) {
        s1 += __shfl_xor_sync(0xffffffffu, s1, o);
        s2 += __shfl_xor_sync(0xffffffffu, s2, o);
    }
    __shared__ float a1[8], a2[8];
    if ((threadIdx.x & 31) == 0) { a1[threadIdx.x >> 5] = s1; a2[threadIdx.x >> 5] = s2; }
    __syncthreads();
    if (threadIdx.x == 0) {
        float t1 = 0.f, t2 = 0.f;
#pragma unroll
        for (int i = 0; i < 8; i++) { t1 += a1[i]; t2 += a2[i]; }
        const float n = (float)(NB * NT);
        const float mu = t1 / n;
        const float var = t2 / n - mu * mu;
        mean[c] = mu;
        istd[c] = rsqrtf(var + 1e-5f);
    }
}

__global__ __launch_bounds__(256) void bn_apply_kernel(
    const float* __restrict__ inpt, const float* __restrict__ h,
    const float* __restrict__ gamma, const float* __restrict__ beta,
    const float* __restrict__ mean, const float* __restrict__ istd,
    float* __restrict__ out)
{
    const int i = blockIdx.x * 256 + threadIdx.x;
    const int c = (i >> 11) & (NC - 1);
    out[i] = inpt[i] + gamma[c] * ((h[i] - mean[c]) * istd[c]) + beta[c];
}

// ---------------- launch -----------------------------------------------------
extern "C" void kernel_launch(void* const* d_in, const int* in_sizes, int n_in,
                              void* d_out, int out_size)
{
    const float* inpt    = (const float*)d_in[0];
    const float* theta_w = (const float*)d_in[1];
    const float* theta_b = (const float*)d_in[2];
    const float* phi_w   = (const float*)d_in[3];
    const float* phi_b   = (const float*)d_in[4];
    const float* gw      = (const float*)d_in[5];
    const float* gb      = (const float*)d_in[6];
    const float* ht_w    = (const float*)d_in[7];
    const float* ht_b    = (const float*)d_in[8];
    const float* bn_g    = (const float*)d_in[9];
    const float* bn_b    = (const float*)d_in[10];
    float* out = (float*)d_out;

    float *p_W, *p_h, *p_mean, *p_istd;
    bf16 *p_thTh, *p_thTl, *p_phTh, *p_phTl, *p_gh, *p_gl, *p_atTh, *p_atTl;
    bf16 *p_inh, *p_inl, *p_twh, *p_twl, *p_pwh, *p_pwl, *p_gwh, *p_gwl, *p_hwh, *p_hwl;
    cudaGetSymbolAddress((void**)&p_W,    g_W);
    cudaGetSymbolAddress((void**)&p_h,    g_h);
    cudaGetSymbolAddress((void**)&p_mean, g_mean);
    cudaGetSymbolAddress((void**)&p_istd, g_istd);
    cudaGetSymbolAddress((void**)&p_thTh, g_thTh); cudaGetSymbolAddress((void**)&p_thTl, g_thTl);
    cudaGetSymbolAddress((void**)&p_phTh, g_phTh); cudaGetSymbolAddress((void**)&p_phTl, g_phTl);
    cudaGetSymbolAddress((void**)&p_gh,   g_gh);   cudaGetSymbolAddress((void**)&p_gl,   g_gl);
    cudaGetSymbolAddress((void**)&p_atTh, g_atTh); cudaGetSymbolAddress((void**)&p_atTl, g_atTl);
    cudaGetSymbolAddress((void**)&p_inh,  g_inh);  cudaGetSymbolAddress((void**)&p_inl,  g_inl);
    cudaGetSymbolAddress((void**)&p_twh,  g_twh);  cudaGetSymbolAddress((void**)&p_twl,  g_twl);
    cudaGetSymbolAddress((void**)&p_pwh,  g_pwh);  cudaGetSymbolAddress((void**)&p_pwl,  g_pwl);
    cudaGetSymbolAddress((void**)&p_gwh,  g_gwh);  cudaGetSymbolAddress((void**)&p_gwl,  g_gwl);
    cudaGetSymbolAddress((void**)&p_hwh,  g_hwh);  cudaGetSymbolAddress((void**)&p_hwl,  g_hwl);

    cudaFuncSetAttribute(tgemm<true,  true,  true,  true,  true,  true >, cudaFuncAttributeMaxDynamicSharedMemorySize, SMEM_BYTES);
    cudaFuncSetAttribute(tgemm<false, false, false, false, true,  false>, cudaFuncAttributeMaxDynamicSharedMemorySize, SMEM_BYTES);
    cudaFuncSetAttribute(tgemm<true,  true,  false, false, false, true >, cudaFuncAttributeMaxDynamicSharedMemorySize, SMEM_BYTES);
    cudaFuncSetAttribute(tgemm<false, false, true,  false, true,  false>, cudaFuncAttributeMaxDynamicSharedMemorySize, SMEM_BYTES);

    const long long sTD = (long long)NT * ND;
    const long long sDT = (long long)ND * NT;
    const long long sCT = (long long)NC * NT;
    const long long sTT = (long long)NT * NT;

    // 0) pre-split inpt + weights into bf16 hi/lo planes
    split_kernel<<<(NB * NC * NT / 4 + 255) / 256, 256>>>((const float4*)inpt, (uint2*)p_inh, (uint2*)p_inl, NB * NC * NT / 4);
    split_kernel<<<(ND * NC / 4 + 255) / 256, 256>>>((const float4*)theta_w, (uint2*)p_twh, (uint2*)p_twl, ND * NC / 4);
    split_kernel<<<(ND * NC / 4 + 255) / 256, 256>>>((const float4*)phi_w,   (uint2*)p_pwh, (uint2*)p_pwl, ND * NC / 4);
    split_kernel<<<(ND * NC / 4 + 255) / 256, 256>>>((const float4*)gw,      (uint2*)p_gwh, (uint2*)p_gwl, ND * NC / 4);
    split_kernel<<<(NC * ND / 4 + 255) / 256, 256>>>((const float4*)ht_w,    (uint2*)p_hwh, (uint2*)p_hwl, NC * ND / 4);

    // 1) fused theta/phi/g projections: M=D, N=T, K=C; B=inpt planes TB; outs = planes
    {
        dim3 grid(NT / 128, ND / 128, 3 * NB);
        tgemm<true, true, true, true, true, true><<<grid, 256, SMEM_BYTES>>>(
            p_twh, p_twl, p_inh, p_inl, p_thTh, p_thTl, theta_b,
            p_pwh, p_pwl, p_phTh, p_phTl, phi_b,
            p_gwh, p_gwl, p_gh, p_gl, gb,
            NC, NC, NT, ND, 0LL, sCT, sTD);
    }

    // 2) W = thT x phT^T : M=N=T, K=D; A,B = planes natural; OUT fp32 (T,S)
    {
        dim3 grid(NT / 128, NT / 128, NB);
        tgemm<false, false, false, false, true, false><<<grid, 256, SMEM_BYTES>>>(
            p_thTh, p_thTl, p_phTh, p_phTl, p_W, nullptr, nullptr,
            nullptr, nullptr, nullptr, nullptr, nullptr,
            nullptr, nullptr, nullptr, nullptr, nullptr,
            ND, ND, ND, NT, sTD, sTD, sTT);
    }

    // 3) softmax rows of W (fp32 in place)
    softmax_kernel<<<NB * NT, 256>>>(p_W);

    // 4) attn^T = (g x P)^T : M=D, N=S, K=T; A=g planes, B=P fp32 TB; OUT planes (S,D)
    {
        dim3 grid(NT / 128, ND / 128, NB);
        tgemm<true, true, false, false, false, true><<<grid, 256, SMEM_BYTES>>>(
            p_gh, p_gl, p_W, nullptr, p_atTh, p_atTl, nullptr,
            nullptr, nullptr, nullptr, nullptr, nullptr,
            nullptr, nullptr, nullptr, nullptr, nullptr,
            NT, NT, NT, ND, sDT, sTT, sTD);
    }

    // 5) h = ht_w x attn : M=C, N=T, K=D; A=ht_w planes, B=atT planes; OUT fp32 (C,T)
    {
        dim3 grid(NT / 128, NC / 128, NB);
        tgemm<false, false, true, false, true, false><<<grid, 256, SMEM_BYTES>>>(
            p_hwh, p_hwl, p_atTh, p_atTl, p_h, nullptr, ht_b,
            nullptr, nullptr, nullptr, nullptr, nullptr,
            nullptr, nullptr, nullptr, nullptr, nullptr,
            ND, ND, ND, NT, 0LL, sTD, sCT);
    }

    // 6) BN stats + apply with residual
    bn_stats_kernel<<<NC, 256>>>(p_h, p_mean, p_istd);
    bn_apply_kernel<<<(NB * NC * NT) / 256, 256>>>(inpt, p_h, bn_g, bn_b,
                                                   p_mean, p_istd, out);
}

// round 14
// speedup vs baseline: 1.4458x; 1.4458x over previous
#include <cuda_runtime.h>
#include <cuda_bf16.h>
#include <cstdint>
#include <math.h>

#define NB 8
#define NC 512
#define ND 256
#define NT 2048

typedef __nv_bfloat16 bf16;

// ---------------- scratch (device globals; no allocations allowed) ----------
__device__ float g_W[(size_t)NB * NT * NT];      // W fp32 (B,T,S)
__device__ float g_h[(size_t)NB * NC * NT];      // h fp32 (B,C,T)
__device__ bf16 g_Ph[(size_t)NB * NT * NT], g_Pl[(size_t)NB * NT * NT];     // P planes
__device__ bf16 g_thTh[(size_t)NB * NT * ND], g_thTl[(size_t)NB * NT * ND]; // theta^T (T,D)
__device__ bf16 g_phTh[(size_t)NB * NT * ND], g_phTl[(size_t)NB * NT * ND]; // phi^T   (T,D)
__device__ bf16 g_gh  [(size_t)NB * ND * NT], g_gl  [(size_t)NB * ND * NT]; // g       (D,T)
__device__ bf16 g_atTh[(size_t)NB * NT * ND], g_atTl[(size_t)NB * NT * ND]; // attn^T  (S,D)
__device__ bf16 g_inh [(size_t)NB * NC * NT], g_inl [(size_t)NB * NC * NT]; // inpt    (C,T)
__device__ bf16 g_twh[ND * NC], g_twl[ND * NC];
__device__ bf16 g_pwh[ND * NC], g_pwl[ND * NC];
__device__ bf16 g_gwh[ND * NC], g_gwl[ND * NC];
__device__ bf16 g_hwh[NC * ND], g_hwl[NC * ND];
__device__ float g_mean[NC];
__device__ float g_istd[NC];

// ---------------- helpers ----------------------------------------------------
__device__ __forceinline__ uint32_t smem_u32(const void* p) {
    uint32_t a;
    asm("{ .reg .u64 t; cvta.to.shared.u64 t, %1; cvt.u32.u64 %0, t; }" : "=r"(a) : "l"(p));
    return a;
}
__device__ __forceinline__ void split2(float x, float y, uint32_t& hi, uint32_t& lo) {
    __nv_bfloat162 h = __floats2bfloat162_rn(x, y);
    float hx = __low2float(h), hy = __high2float(h);
    __nv_bfloat162 l = __floats2bfloat162_rn(x - hx, y - hy);
    hi = *reinterpret_cast<uint32_t*>(&h);
    lo = *reinterpret_cast<uint32_t*>(&l);
}
__device__ __forceinline__ void mma16(float* d, const uint32_t* a, const uint32_t* b) {
    asm volatile(
        "mma.sync.aligned.m16n8k16.row.col.f32.bf16.bf16.f32 "
        "{%0,%1,%2,%3}, {%4,%5,%6,%7}, {%8,%9}, {%0,%1,%2,%3};"
        : "+f"(d[0]), "+f"(d[1]), "+f"(d[2]), "+f"(d[3])
        : "r"(a[0]), "r"(a[1]), "r"(a[2]), "r"(a[3]), "r"(b[0]), "r"(b[1]));
}
#define CP16(dst, src) \
    asm volatile("cp.async.cg.shared.global [%0], [%1], 16;" :: "r"(dst), "l"(src) : "memory")
#define CP_COMMIT() asm volatile("cp.async.commit_group;" ::: "memory")
#define CP_WAIT(n)  asm volatile("cp.async.wait_group %0;" :: "n"(n) : "memory")
#define LDSM_X4(R, addr) \
    asm volatile("ldmatrix.sync.aligned.m8n8.x4.shared.b16 {%0,%1,%2,%3}, [%4];" \
        : "=r"((R)[0]), "=r"((R)[1]), "=r"((R)[2]), "=r"((R)[3]) : "r"(addr))
#define LDSM_X4T(R, addr) \
    asm volatile("ldmatrix.sync.aligned.m8n8.x4.trans.shared.b16 {%0,%1,%2,%3}, [%4];" \
        : "=r"((R)[0]), "=r"((R)[1]), "=r"((R)[2]), "=r"((R)[3]) : "r"(addr))

// SMEM: 3 stages x 32KB.  Stage: A 16KB (128 rows x [hi 64B | lo 64B], swizzled),
// B 16KB (natural: same as A; TB: [hi 32 k-rows x 256B][lo 8KB], swizzled).
#define STAGE_BYTES 32768
static constexpr int SMEM_BYTES = 3 * STAGE_BYTES;   // 98304

// ---------------- bf16x3 GEMM: cp.async + ldmatrix, 3-stage pipeline ---------
// All operands bf16 hi/lo planes. A natural (M,K) lda.
// TB=false: B natural (N,K) ldb. TB=true: B (K,N) ldb (k-rows n-contiguous).
// OUTK=0: C fp32 natural (M,N) ldc. OUTK=2: C planes transposed C[n*ldc+m] via smem stage.
// FUSED3: bz = op*NB+b; op 0,1 -> staged planes (ldc=ND); op 2 -> natural planes (ldc=NT).
template <bool TB, bool BIAS, bool FUSED3, int OUTK>
__global__ __launch_bounds__(256, 2) void tgemm(
    const bf16* __restrict__ Ahi, const bf16* __restrict__ Alo,
    const bf16* __restrict__ Bhi, const bf16* __restrict__ Blo,
    float* __restrict__ Cf, bf16* __restrict__ Chg, bf16* __restrict__ Clg,
    const float* __restrict__ bias,
    const bf16* A1hi, const bf16* A1lo, bf16* C1hg, bf16* C1lg, const float* bias1,
    const bf16* A2hi, const bf16* A2lo, bf16* C2hg, bf16* C2lg, const float* bias2,
    int K, int lda, int ldb, int ldc, long long sA, long long sB, long long sC)
{
    extern __shared__ char smem[];
    const uint32_t sb = smem_u32(smem);
    const int tid = threadIdx.x;
    const int lane = tid & 31;
    const int wid = tid >> 5;
    const int warpM = wid >> 2, warpN = wid & 3;
    const int g4 = lane >> 2, tig = lane & 3;
    const int sub = lane >> 3, l7 = lane & 7;

    int bz = blockIdx.z;
    int opsel = 0;
    if (FUSED3) {
        opsel = bz >> 3;
        bz &= 7;
        if (opsel == 1) { Ahi = A1hi; Alo = A1lo; Chg = C1hg; Clg = C1lg; bias = bias1; }
        else if (opsel == 2) { Ahi = A2hi; Alo = A2lo; Chg = C2hg; Clg = C2lg; bias = bias2; ldc = NT; }
    }
    const int m0 = blockIdx.y * 128, n0 = blockIdx.x * 128;
    Ahi += (long long)bz * sA;  Alo += (long long)bz * sA;
    Bhi += (long long)bz * sB;  Blo += (long long)bz * sB;
    if (OUTK == 0) Cf += (long long)bz * sC;
    else { Chg += (long long)bz * sC; Clg += (long long)bz * sC; }

    float acc[4][4][4];
#pragma unroll
    for (int a = 0; a < 4; a++)
#pragma unroll
        for (int b = 0; b < 4; b++)
#pragma unroll
            for (int c = 0; c < 4; c++) acc[a][b][c] = 0.f;

    const int nch = K >> 5;

    auto issueChunk = [&](int ch, int stg) {
        const uint32_t Ab = sb + stg * STAGE_BYTES;
        const uint32_t Bb = Ab + 16384;
#pragma unroll
        for (int j = 0; j < 4; j++) {
            const int e = tid + j * 256;
            const int row = e >> 3, c8 = e & 7;
            const bf16* src = (c8 < 4 ? Ahi : Alo) + (size_t)(m0 + row) * lda + ch * 32 + (c8 & 3) * 8;
            const uint32_t dst = Ab + row * 128 + ((c8 * 16) ^ ((row & 7) << 4));
            CP16(dst, src);
        }
        if (TB) {
#pragma unroll
            for (int j = 0; j < 4; j++) {
                const int e = tid + j * 256;
                const int kr = e >> 5, c = e & 31, pl = c >> 4, c16 = c & 15;
                const bf16* src = (pl ? Blo : Bhi) + (size_t)(ch * 32 + kr) * ldb + n0 + c16 * 8;
                const uint32_t dst = Bb + pl * 8192 + kr * 256 + ((c16 * 16) ^ ((kr & 7) << 4));
                CP16(dst, src);
            }
        } else {
#pragma unroll
            for (int j = 0; j < 4; j++) {
                const int e = tid + j * 256;
                const int row = e >> 3, c8 = e & 7;
                const bf16* src = (c8 < 4 ? Bhi : Blo) + (size_t)(n0 + row) * ldb + ch * 32 + (c8 & 3) * 8;
                const uint32_t dst = Bb + row * 128 + ((c8 * 16) ^ ((row & 7) << 4));
                CP16(dst, src);
            }
        }
    };

    auto ldAfrag = [&](uint32_t Ab, int ks, int plane, int mf, uint32_t* R) {
        const int r = warpM * 64 + mf * 16 + l7 + ((sub & 1) << 3);
        const int kb = plane * 64 + ks * 32 + ((sub >> 1) << 4);
        LDSM_X4(R, Ab + r * 128 + (kb ^ ((r & 7) << 4)));
    };
    auto ldBfrag = [&](uint32_t Bb, int ks, int plane, int pair, uint32_t* R) {
        if (TB) {
            const int kr = ks * 16 + ((sub & 1) << 3) + l7;
            const int nb = (warpN * 32 + pair * 16 + ((sub >> 1) << 3)) * 2;
            LDSM_X4T(R, Bb + plane * 8192 + kr * 256 + (nb ^ ((kr & 7) << 4)));
        } else {
            const int n = warpN * 32 + pair * 16 + ((sub >> 1) << 3) + l7;
            const int kb = plane * 64 + ks * 32 + ((sub & 1) << 4);
            LDSM_X4(R, Bb + n * 128 + (kb ^ ((n & 7) << 4)));
        }
    };

    auto compute = [&](int stg) {
        const uint32_t Ab = sb + stg * STAGE_BYTES;
        const uint32_t Bb = Ab + 16384;
#pragma unroll
        for (int ks = 0; ks < 2; ks++) {
            uint32_t afh[4][4];
#pragma unroll
            for (int mf = 0; mf < 4; mf++) ldAfrag(Ab, ks, 0, mf, afh[mf]);
            uint32_t bfh[2][4];        // bfh[p] = {b0(nf=2p), b1(nf=2p), b0(2p+1), b1(2p+1)}
            ldBfrag(Bb, ks, 0, 0, bfh[0]);
            ldBfrag(Bb, ks, 0, 1, bfh[1]);
            // term 1: hiA * hiB
#pragma unroll
            for (int mf = 0; mf < 4; mf++)
#pragma unroll
                for (int nf = 0; nf < 4; nf++)
                    mma16(acc[mf][nf], afh[mf], &bfh[nf >> 1][(nf & 1) * 2]);
            // term 2: loA * hiB
#pragma unroll
            for (int mf = 0; mf < 4; mf++) {
                uint32_t t[4];
                ldAfrag(Ab, ks, 1, mf, t);
#pragma unroll
                for (int nf = 0; nf < 4; nf++)
                    mma16(acc[mf][nf], t, &bfh[nf >> 1][(nf & 1) * 2]);
            }
            // term 3: hiA * loB
#pragma unroll
            for (int p = 0; p < 2; p++) {
                uint32_t t[4];
                ldBfrag(Bb, ks, 1, p, t);
#pragma unroll
                for (int mf = 0; mf < 4; mf++) {
                    mma16(acc[mf][p * 2 + 0], afh[mf], &t[0]);
                    mma16(acc[mf][p * 2 + 1], afh[mf], &t[2]);
                }
            }
        }
    };

    // ---- pipeline: prefetch distance 2, wait_group + 1 barrier per chunk ----
    issueChunk(0, 0); CP_COMMIT();
    if (nch > 1) { issueChunk(1, 1); CP_COMMIT(); }
    int stg = 0;
    for (int ch = 0; ch < nch; ch++) {
        if (ch + 1 < nch) CP_WAIT(1); else CP_WAIT(0);
        __syncthreads();
        if (ch + 2 < nch) {
            int s2 = stg + 2; if (s2 >= 3) s2 -= 3;
            issueChunk(ch + 2, s2); CP_COMMIT();
        }
        compute(stg);
        if (++stg == 3) stg = 0;
    }

    // ---- epilogue ----
    if (OUTK == 0) {
#pragma unroll
        for (int mf = 0; mf < 4; mf++) {
            const int m = m0 + warpM * 64 + mf * 16 + g4;
            const float bv0 = BIAS ? bias[m] : 0.f;
            const float bv1 = BIAS ? bias[m + 8] : 0.f;
#pragma unroll
            for (int nf = 0; nf < 4; nf++) {
                const int n = n0 + warpN * 32 + nf * 8 + 2 * tig;
                *(float2*)(Cf + (size_t)m * ldc + n) =
                    make_float2(acc[mf][nf][0] + bv0, acc[mf][nf][1] + bv0);
                *(float2*)(Cf + (size_t)(m + 8) * ldc + n) =
                    make_float2(acc[mf][nf][2] + bv1, acc[mf][nf][3] + bv1);
            }
        }
    } else if (FUSED3 && opsel == 2) {
        // natural planes (D,T): packed-pair u32 stores
#pragma unroll
        for (int mf = 0; mf < 4; mf++) {
            const int m = m0 + warpM * 64 + mf * 16 + g4;
            const float bv0 = BIAS ? bias[m] : 0.f;
            const float bv1 = BIAS ? bias[m + 8] : 0.f;
#pragma unroll
            for (int nf = 0; nf < 4; nf++) {
                const int n = n0 + warpN * 32 + nf * 8 + 2 * tig;
                uint32_t h01, l01, h23, l23;
                split2(acc[mf][nf][0] + bv0, acc[mf][nf][1] + bv0, h01, l01);
                split2(acc[mf][nf][2] + bv1, acc[mf][nf][3] + bv1, h23, l23);
                *(uint32_t*)((unsigned short*)Chg + (size_t)m * ldc + n) = h01;
                *(uint32_t*)((unsigned short*)Clg + (size_t)m * ldc + n) = l01;
                *(uint32_t*)((unsigned short*)Chg + (size_t)(m + 8) * ldc + n) = h23;
                *(uint32_t*)((unsigned short*)Clg + (size_t)(m + 8) * ldc + n) = l23;
            }
        }
    } else {
        // staged transposed planes: stage fp32 in smem, split on coalesced copy-out
        __syncthreads();
        float* stgm = (float*)smem;                 // [128 n][stride 130]
#pragma unroll
        for (int mf = 0; mf < 4; mf++) {
            const int ml = warpM * 64 + mf * 16 + g4;
            const float bv0 = BIAS ? bias[m0 + ml] : 0.f;
            const float bv1 = BIAS ? bias[m0 + ml + 8] : 0.f;
#pragma unroll
            for (int nf = 0; nf < 4; nf++) {
                const int nl = warpN * 32 + nf * 8 + 2 * tig;
                stgm[nl * 130 + ml]           = acc[mf][nf][0] + bv0;
                stgm[(nl + 1) * 130 + ml]     = acc[mf][nf][1] + bv0;
                stgm[nl * 130 + ml + 8]       = acc[mf][nf][2] + bv1;
                stgm[(nl + 1) * 130 + ml + 8] = acc[mf][nf][3] + bv1;
            }
        }
        __syncthreads();
#pragma unroll
        for (int j = 0; j < 8; j++) {
            const int e = tid + j * 256;
            const int row = e >> 4, seg = e & 15;
            const float* src = stgm + row * 130 + seg * 8;
            uint32_t h[4], l[4];
            split2(src[0], src[1], h[0], l[0]);
            split2(src[2], src[3], h[1], l[1]);
            split2(src[4], src[5], h[2], l[2]);
            split2(src[6], src[7], h[3], l[3]);
            const size_t off = (size_t)(n0 + row) * ldc + m0 + seg * 8;
            *(uint4*)((unsigned short*)Chg + off) = make_uint4(h[0], h[1], h[2], h[3]);
            *(uint4*)((unsigned short*)Clg + off) = make_uint4(l[0], l[1], l[2], l[3]);
        }
    }
}

// ---------------- fp32 -> bf16 hi/lo plane split ------------------------------
__global__ __launch_bounds__(256) void split_kernel(
    const float4* __restrict__ src, uint2* __restrict__ hi, uint2* __restrict__ lo, int n4)
{
    const int i = blockIdx.x * 256 + threadIdx.x;
    if (i >= n4) return;
    const float4 v = src[i];
    uint32_t h0, l0, h1, l1;
    split2(v.x, v.y, h0, l0);
    split2(v.z, v.w, h1, l1);
    hi[i] = make_uint2(h0, h1);
    lo[i] = make_uint2(l0, l1);
}

// ---------------- softmax: W fp32 rows -> P bf16 hi/lo planes ----------------
__global__ __launch_bounds__(256) void softmax_kernel(
    const float* __restrict__ W, bf16* __restrict__ Ph, bf16* __restrict__ Pl)
{
    const float4* p4 = (const float4*)(W + (size_t)blockIdx.x * NT);
    const int t = threadIdx.x;
    float4 a = p4[t], b = p4[t + 256];
    float x[8] = {a.x, a.y, a.z, a.w, b.x, b.y, b.z, b.w};

    float m = x[0];
#pragma unroll
    for (int r = 1; r < 8; r++) m = fmaxf(m, x[r]);
#pragma unroll
    for (int o = 16; o; o >>= 1) m = fmaxf(m, __shfl_xor_sync(0xffffffffu, m, o));
    __shared__ float smax[8], ssum[8];
    if ((t & 31) == 0) smax[t >> 5] = m;
    __syncthreads();
    m = smax[0];
#pragma unroll
    for (int i = 1; i < 8; i++) m = fmaxf(m, smax[i]);
    float e[8], s = 0.f;
#pragma unroll
    for (int r = 0; r < 8; r++) { e[r] = __expf(x[r] - m); s += e[r]; }
#pragma unroll
    for (int o = 16; o; o >>= 1) s += __shfl_xor_sync(0xffffffffu, s, o);
    if ((t & 31) == 0) ssum[t >> 5] = s;
    __syncthreads();
    s = ssum[0];
#pragma unroll
    for (int i = 1; i < 8; i++) s += ssum[i];
    const float inv = 1.f / s;

    uint2* ph2 = (uint2*)(Ph + (size_t)blockIdx.x * NT);
    uint2* pl2 = (uint2*)(Pl + (size_t)blockIdx.x * NT);
    uint32_t h0, l0, h1, l1;
    split2(e[0] * inv, e[1] * inv, h0, l0);
    split2(e[2] * inv, e[3] * inv, h1, l1);
    ph2[t] = make_uint2(h0, h1);
    pl2[t] = make_uint2(l0, l1);
    split2(e[4] * inv, e[5] * inv, h0, l0);
    split2(e[6] * inv, e[7] * inv, h1, l1);
    ph2[t + 256] = make_uint2(h0, h1);
    pl2[t + 256] = make_uint2(l0, l1);
}

// ---------------- BatchNorm stats + apply ------------------------------------
__global__ __launch_bounds__(256) void bn_stats_kernel(
    const float* __restrict__ h, float* __restrict__ mean, float* __restrict__ istd)
{
    const int c = blockIdx.x;
    float s1 = 0.f, s2 = 0.f;
    for (int i = threadIdx.x; i < NB * NT; i += 256) {
        const int b = i >> 11, t = i & (NT - 1);
        const float v = h[(size_t)b * NC * NT + (size_t)c * NT + t];
        s1 += v; s2 += v * v;
    }
#pragma unroll
    for (int o = 16; o; o >>= 1) {
        s1 += __shfl_xor_sync(0xffffffffu, s1, o);
        s2 += __shfl_xor_sync(0xffffffffu, s2, o);
    }
    __shared__ float a1[8], a2[8];
    if ((threadIdx.x & 31) == 0) { a1[threadIdx.x >> 5] = s1; a2[threadIdx.x >> 5] = s2; }
    __syncthreads();
    if (threadIdx.x == 0) {
        float t1 = 0.f, t2 = 0.f;
#pragma unroll
        for (int i = 0; i < 8; i++) { t1 += a1[i]; t2 += a2[i]; }
        const float n = (float)(NB * NT);
        const float mu = t1 / n;
        const float var = t2 / n - mu * mu;
        mean[c] = mu;
        istd[c] = rsqrtf(var + 1e-5f);
    }
}

__global__ __launch_bounds__(256) void bn_apply_kernel(
    const float* __restrict__ inpt, const float* __restrict__ h,
    const float* __restrict__ gamma, const float* __restrict__ beta,
    const float* __restrict__ mean, const float* __restrict__ istd,
    float* __restrict__ out)
{
    const int i = blockIdx.x * 256 + threadIdx.x;
    const int c = (i >> 11) & (NC - 1);
    out[i] = inpt[i] + gamma[c] * ((h[i] - mean[c]) * istd[c]) + beta[c];
}

// ---------------- launch -----------------------------------------------------
extern "C" void kernel_launch(void* const* d_in, const int* in_sizes, int n_in,
                              void* d_out, int out_size)
{
    const float* inpt    = (const float*)d_in[0];
    const float* theta_w = (const float*)d_in[1];
    const float* theta_b = (const float*)d_in[2];
    const float* phi_w   = (const float*)d_in[3];
    const float* phi_b   = (const float*)d_in[4];
    const float* gw      = (const float*)d_in[5];
    const float* gb      = (const float*)d_in[6];
    const float* ht_w    = (const float*)d_in[7];
    const float* ht_b    = (const float*)d_in[8];
    const float* bn_g    = (const float*)d_in[9];
    const float* bn_b    = (const float*)d_in[10];
    float* out = (float*)d_out;

    float *p_W, *p_h, *p_mean, *p_istd;
    bf16 *p_Ph, *p_Pl, *p_thTh, *p_thTl, *p_phTh, *p_phTl, *p_gh, *p_gl, *p_atTh, *p_atTl;
    bf16 *p_inh, *p_inl, *p_twh, *p_twl, *p_pwh, *p_pwl, *p_gwh, *p_gwl, *p_hwh, *p_hwl;
    cudaGetSymbolAddress((void**)&p_W,    g_W);
    cudaGetSymbolAddress((void**)&p_h,    g_h);
    cudaGetSymbolAddress((void**)&p_mean, g_mean);
    cudaGetSymbolAddress((void**)&p_istd, g_istd);
    cudaGetSymbolAddress((void**)&p_Ph,   g_Ph);   cudaGetSymbolAddress((void**)&p_Pl,   g_Pl);
    cudaGetSymbolAddress((void**)&p_thTh, g_thTh); cudaGetSymbolAddress((void**)&p_thTl, g_thTl);
    cudaGetSymbolAddress((void**)&p_phTh, g_phTh); cudaGetSymbolAddress((void**)&p_phTl, g_phTl);
    cudaGetSymbolAddress((void**)&p_gh,   g_gh);   cudaGetSymbolAddress((void**)&p_gl,   g_gl);
    cudaGetSymbolAddress((void**)&p_atTh, g_atTh); cudaGetSymbolAddress((void**)&p_atTl, g_atTl);
    cudaGetSymbolAddress((void**)&p_inh,  g_inh);  cudaGetSymbolAddress((void**)&p_inl,  g_inl);
    cudaGetSymbolAddress((void**)&p_twh,  g_twh);  cudaGetSymbolAddress((void**)&p_twl,  g_twl);
    cudaGetSymbolAddress((void**)&p_pwh,  g_pwh);  cudaGetSymbolAddress((void**)&p_pwl,  g_pwl);
    cudaGetSymbolAddress((void**)&p_gwh,  g_gwh);  cudaGetSymbolAddress((void**)&p_gwl,  g_gwl);
    cudaGetSymbolAddress((void**)&p_hwh,  g_hwh);  cudaGetSymbolAddress((void**)&p_hwl,  g_hwl);

    cudaFuncSetAttribute(tgemm<true,  true,  true,  2>, cudaFuncAttributeMaxDynamicSharedMemorySize, SMEM_BYTES);
    cudaFuncSetAttribute(tgemm<false, false, false, 0>, cudaFuncAttributeMaxDynamicSharedMemorySize, SMEM_BYTES);
    cudaFuncSetAttribute(tgemm<true,  false, false, 2>, cudaFuncAttributeMaxDynamicSharedMemorySize, SMEM_BYTES);
    cudaFuncSetAttribute(tgemm<false, true,  false, 0>, cudaFuncAttributeMaxDynamicSharedMemorySize, SMEM_BYTES);

    const long long sTD = (long long)NT * ND;
    const long long sDT = (long long)ND * NT;
    const long long sCT = (long long)NC * NT;
    const long long sTT = (long long)NT * NT;

    // 0) pre-split inpt + weights
    split_kernel<<<(NB * NC * NT / 4 + 255) / 256, 256>>>((const float4*)inpt, (uint2*)p_inh, (uint2*)p_inl, NB * NC * NT / 4);
    split_kernel<<<(ND * NC / 4 + 255) / 256, 256>>>((const float4*)theta_w, (uint2*)p_twh, (uint2*)p_twl, ND * NC / 4);
    split_kernel<<<(ND * NC / 4 + 255) / 256, 256>>>((const float4*)phi_w,   (uint2*)p_pwh, (uint2*)p_pwl, ND * NC / 4);
    split_kernel<<<(ND * NC / 4 + 255) / 256, 256>>>((const float4*)gw,      (uint2*)p_gwh, (uint2*)p_gwl, ND * NC / 4);
    split_kernel<<<(NC * ND / 4 + 255) / 256, 256>>>((const float4*)ht_w,    (uint2*)p_hwh, (uint2*)p_hwl, NC * ND / 4);

    // 1) fused theta/phi/g: M=D, N=T, K=C; B = inpt planes (TB); 768 CTAs
    {
        dim3 grid(NT / 128, ND / 128, 3 * NB);
        tgemm<true, true, true, 2><<<grid, 256, SMEM_BYTES>>>(
            p_twh, p_twl, p_inh, p_inl, nullptr, p_thTh, p_thTl, theta_b,
            p_pwh, p_pwl, p_phTh, p_phTl, phi_b,
            p_gwh, p_gwl, p_gh, p_gl, gb,
            NC, NC, NT, ND, 0LL, sCT, sTD);
    }

    // 2) W = thT x phT^T : M=N=T, K=D; both natural planes; OUT fp32 (T,S)
    {
        dim3 grid(NT / 128, NT / 128, NB);
        tgemm<false, false, false, 0><<<grid, 256, SMEM_BYTES>>>(
            p_thTh, p_thTl, p_phTh, p_phTl, p_W, nullptr, nullptr, nullptr,
            nullptr, nullptr, nullptr, nullptr, nullptr,
            nullptr, nullptr, nullptr, nullptr, nullptr,
            ND, ND, ND, NT, sTD, sTD, sTT);
    }

    // 3) softmax rows of W -> P planes
    softmax_kernel<<<NB * NT, 256>>>(p_W, p_Ph, p_Pl);

    // 4) attn^T = (g x P)^T : M=D, N=S, K=T; B = P planes (TB); OUT staged planes (S,D)
    {
        dim3 grid(NT / 128, ND / 128, NB);
        tgemm<true, false, false, 2><<<grid, 256, SMEM_BYTES>>>(
            p_gh, p_gl, p_Ph, p_Pl, nullptr, p_atTh, p_atTl, nullptr,
            nullptr, nullptr, nullptr, nullptr, nullptr,
            nullptr, nullptr, nullptr, nullptr, nullptr,
            NT, NT, NT, ND, sDT, sTT, sTD);
    }

    // 5) h = ht_w x attn : M=C, N=T, K=D; B = attn^T planes natural; OUT fp32 (C,T)
    {
        dim3 grid(NT / 128, NC / 128, NB);
        tgemm<false, true, false, 0><<<grid, 256, SMEM_BYTES>>>(
            p_hwh, p_hwl, p_atTh, p_atTl, p_h, nullptr, nullptr, ht_b,
            nullptr, nullptr, nullptr, nullptr, nullptr,
            nullptr, nullptr, nullptr, nullptr, nullptr,
            ND, ND, ND, NT, 0LL, sTD, sCT);
    }

    // 6) BN stats + apply with residual
    bn_stats_kernel<<<NC, 256>>>(p_h, p_mean, p_istd);
    bn_apply_kernel<<<(NB * NC * NT) / 256, 256>>>(inpt, p_h, bn_g, bn_b,
                                                   p_mean, p_istd, out);
}

// round 16
// speedup vs baseline: 1.6318x; 1.1286x over previous
#include <cuda_runtime.h>
#include <cuda_bf16.h>
#include <cstdint>
#include <math.h>

#define NB 8
#define NC 512
#define ND 256
#define NT 2048

typedef __nv_bfloat16 bf16;

// ---------------- scratch (device globals; no allocations allowed) ----------
__device__ float g_W[(size_t)NB * NT * NT];      // W fp32 (B,T,S)
__device__ float g_h[(size_t)NB * NC * NT];      // h fp32 (B,C,T)
__device__ bf16 g_Ph[(size_t)NB * NT * NT], g_Pl[(size_t)NB * NT * NT];     // P planes
__device__ bf16 g_thTh[(size_t)NB * NT * ND], g_thTl[(size_t)NB * NT * ND]; // theta^T (T,D)
__device__ bf16 g_phTh[(size_t)NB * NT * ND], g_phTl[(size_t)NB * NT * ND]; // phi^T   (T,D)
__device__ bf16 g_gh  [(size_t)NB * ND * NT], g_gl  [(size_t)NB * ND * NT]; // g       (D,T)
__device__ bf16 g_atTh[(size_t)NB * NT * ND], g_atTl[(size_t)NB * NT * ND]; // attn^T  (S,D)
__device__ bf16 g_inh [(size_t)NB * NC * NT], g_inl [(size_t)NB * NC * NT]; // inpt    (C,T)
__device__ bf16 g_twh[ND * NC], g_twl[ND * NC];
__device__ bf16 g_pwh[ND * NC], g_pwl[ND * NC];
__device__ bf16 g_gwh[ND * NC], g_gwl[ND * NC];
__device__ bf16 g_hwh[NC * ND], g_hwl[NC * ND];
__device__ float g_mean[NC];
__device__ float g_istd[NC];

// ---------------- helpers ----------------------------------------------------
__device__ __forceinline__ uint32_t smem_u32(const void* p) {
    uint32_t a;
    asm("{ .reg .u64 t; cvta.to.shared.u64 t, %1; cvt.u32.u64 %0, t; }" : "=r"(a) : "l"(p));
    return a;
}
__device__ __forceinline__ void split2(float x, float y, uint32_t& hi, uint32_t& lo) {
    __nv_bfloat162 h = __floats2bfloat162_rn(x, y);
    float hx = __low2float(h), hy = __high2float(h);
    __nv_bfloat162 l = __floats2bfloat162_rn(x - hx, y - hy);
    hi = *reinterpret_cast<uint32_t*>(&h);
    lo = *reinterpret_cast<uint32_t*>(&l);
}
__device__ __forceinline__ void mma16(float* d, const uint32_t* a, const uint32_t* b) {
    asm volatile(
        "mma.sync.aligned.m16n8k16.row.col.f32.bf16.bf16.f32 "
        "{%0,%1,%2,%3}, {%4,%5,%6,%7}, {%8,%9}, {%0,%1,%2,%3};"
        : "+f"(d[0]), "+f"(d[1]), "+f"(d[2]), "+f"(d[3])
        : "r"(a[0]), "r"(a[1]), "r"(a[2]), "r"(a[3]), "r"(b[0]), "r"(b[1]));
}
#define CP16(dst, src) \
    asm volatile("cp.async.cg.shared.global [%0], [%1], 16;" :: "r"(dst), "l"(src) : "memory")
#define CP_COMMIT() asm volatile("cp.async.commit_group;" ::: "memory")
#define CP_WAIT(n)  asm volatile("cp.async.wait_group %0;" :: "n"(n) : "memory")
#define LDSM_X4(R, addr) \
    asm volatile("ldmatrix.sync.aligned.m8n8.x4.shared.b16 {%0,%1,%2,%3}, [%4];" \
        : "=r"((R)[0]), "=r"((R)[1]), "=r"((R)[2]), "=r"((R)[3]) : "r"(addr))
#define LDSM_X4T(R, addr) \
    asm volatile("ldmatrix.sync.aligned.m8n8.x4.trans.shared.b16 {%0,%1,%2,%3}, [%4];" \
        : "=r"((R)[0]), "=r"((R)[1]), "=r"((R)[2]), "=r"((R)[3]) : "r"(addr))

// SMEM: 3 stages x 32KB. Stage: A 16KB, B 16KB (B region at stage base + 16384).
#define STAGE_BYTES 32768
static constexpr int SMEM_BYTES = 3 * STAGE_BYTES;   // 98304

// ---------------- bf16x3 GEMM: cp.async + ldmatrix, 3-stage pipeline ---------
// All operands bf16 hi/lo planes. A natural (M,K) lda.
// TB=false: B natural (N,K) ldb. TB=true: B (K,N) ldb.
// OUTK=0: C fp32 natural (M,N) ldc. OUTK=2: C planes transposed via smem stage.
// FUSED3: bz = op*NB+b; op 0,1 -> staged planes (ldc=ND); op 2 -> natural planes (ldc=NT).
template <bool TB, bool BIAS, bool FUSED3, int OUTK>
__global__ __launch_bounds__(256, 2) void tgemm(
    const bf16* __restrict__ Ahi, const bf16* __restrict__ Alo,
    const bf16* __restrict__ Bhi, const bf16* __restrict__ Blo,
    float* __restrict__ Cf, bf16* __restrict__ Chg, bf16* __restrict__ Clg,
    const float* __restrict__ bias,
    const bf16* A1hi, const bf16* A1lo, bf16* C1hg, bf16* C1lg, const float* bias1,
    const bf16* A2hi, const bf16* A2lo, bf16* C2hg, bf16* C2lg, const float* bias2,
    int K, int lda, int ldb, int ldc, long long sA, long long sB, long long sC)
{
    extern __shared__ char smem[];
    const uint32_t sb = smem_u32(smem);
    const int tid = threadIdx.x;
    const int lane = tid & 31;
    const int wid = tid >> 5;
    const int warpM = wid >> 2, warpN = wid & 3;
    const int g4 = lane >> 2, tig = lane & 3;
    const int sub = lane >> 3, l7 = lane & 7;

    int bz = blockIdx.z;
    int opsel = 0;
    if (FUSED3) {
        opsel = bz >> 3;
        bz &= 7;
        if (opsel == 1) { Ahi = A1hi; Alo = A1lo; Chg = C1hg; Clg = C1lg; bias = bias1; }
        else if (opsel == 2) { Ahi = A2hi; Alo = A2lo; Chg = C2hg; Clg = C2lg; bias = bias2; ldc = NT; }
    }
    const int m0 = blockIdx.y * 128, n0 = blockIdx.x * 128;
    Ahi += (long long)bz * sA;  Alo += (long long)bz * sA;
    Bhi += (long long)bz * sB;  Blo += (long long)bz * sB;
    if (OUTK == 0) Cf += (long long)bz * sC;
    else { Chg += (long long)bz * sC; Clg += (long long)bz * sC; }

    float acc[4][4][4];
#pragma unroll
    for (int a = 0; a < 4; a++)
#pragma unroll
        for (int b = 0; b < 4; b++)
#pragma unroll
            for (int c = 0; c < 4; c++) acc[a][b][c] = 0.f;

    const int nch = K >> 5;

    // ---- hoisted per-thread addressing (linear in j and chunk) ----
    const int rowA = tid >> 3, c8 = tid & 7;
    const bf16* srcA = (c8 < 4 ? Ahi : Alo) + (size_t)(m0 + rowA) * lda + (c8 & 3) * 8;
    const uint32_t dstA0 = rowA * 128 + ((c8 * 16) ^ ((rowA & 7) << 4));
    const int ldaJ = 32 * lda;                       // A j-step (elems)

    const bf16* srcB;
    uint32_t dstB0;                                   // includes +16384 B-region offset
    int ldbJ, ldbC;                                   // B j-step / chunk-step (elems)
    if (TB) {
        const int kr = tid >> 5, c = tid & 31, pl = c >> 4, c16 = c & 15;
        srcB = (pl ? Blo : Bhi) + (size_t)kr * ldb + n0 + c16 * 8;
        dstB0 = 16384 + pl * 8192 + kr * 256 + ((c16 * 16) ^ ((kr & 7) << 4));
        ldbJ = 8 * ldb; ldbC = 32 * ldb;
    } else {
        srcB = (c8 < 4 ? Bhi : Blo) + (size_t)(n0 + rowA) * ldb + (c8 & 3) * 8;
        dstB0 = 16384 + dstA0;
        ldbJ = 32 * ldb; ldbC = 32;
    }

    auto issueA = [&](uint32_t base) {
#pragma unroll
        for (int j = 0; j < 4; j++)
            CP16(base + dstA0 + j * 4096, srcA + (size_t)j * ldaJ);
        srcA += 32;
    };
    auto issueB = [&](uint32_t base) {
        const int jstride = TB ? 2048 : 4096;
#pragma unroll
        for (int j = 0; j < 4; j++)
            CP16(base + dstB0 + j * jstride, srcB + (size_t)j * ldbJ);
        srcB += ldbC;
    };

    auto ldAfrag = [&](uint32_t Ab, int ks, int plane, int mf, uint32_t* R) {
        const int r = warpM * 64 + mf * 16 + l7 + ((sub & 1) << 3);
        const int kb = plane * 64 + ks * 32 + ((sub >> 1) << 4);
        LDSM_X4(R, Ab + r * 128 + (kb ^ ((r & 7) << 4)));
    };
    auto ldBfrag = [&](uint32_t Bb, int ks, int plane, int pair, uint32_t* R) {
        if (TB) {
            const int kr = ks * 16 + ((sub & 1) << 3) + l7;
            const int nb = (warpN * 32 + pair * 16 + ((sub >> 1) << 3)) * 2;
            LDSM_X4T(R, Bb + plane * 8192 + kr * 256 + (nb ^ ((kr & 7) << 4)));
        } else {
            const int n = warpN * 32 + pair * 16 + ((sub >> 1) << 3) + l7;
            const int kb = plane * 64 + ks * 32 + ((sub & 1) << 4);
            LDSM_X4(R, Bb + n * 128 + (kb ^ ((n & 7) << 4)));
        }
    };

    auto computeKs = [&](uint32_t Ab, uint32_t Bb, int ks) {
        uint32_t afh[4][4];
#pragma unroll
        for (int mf = 0; mf < 4; mf++) ldAfrag(Ab, ks, 0, mf, afh[mf]);
        uint32_t bfh[2][4];
        ldBfrag(Bb, ks, 0, 0, bfh[0]);
        ldBfrag(Bb, ks, 0, 1, bfh[1]);
#pragma unroll
        for (int mf = 0; mf < 4; mf++)
#pragma unroll
            for (int nf = 0; nf < 4; nf++)
                mma16(acc[mf][nf], afh[mf], &bfh[nf >> 1][(nf & 1) * 2]);
#pragma unroll
        for (int mf = 0; mf < 4; mf++) {
            uint32_t t[4];
            ldAfrag(Ab, ks, 1, mf, t);
#pragma unroll
            for (int nf = 0; nf < 4; nf++)
                mma16(acc[mf][nf], t, &bfh[nf >> 1][(nf & 1) * 2]);
        }
#pragma unroll
        for (int p = 0; p < 2; p++) {
            uint32_t t[4];
            ldBfrag(Bb, ks, 1, p, t);
#pragma unroll
            for (int mf = 0; mf < 4; mf++) {
                mma16(acc[mf][p * 2 + 0], afh[mf], &t[0]);
                mma16(acc[mf][p * 2 + 1], afh[mf], &t[2]);
            }
        }
    };

    // ---- pipeline: prefetch distance 2; prefetch interleaved into compute ----
    issueA(sb); issueB(sb); CP_COMMIT();
    if (nch > 1) { issueA(sb + STAGE_BYTES); issueB(sb + STAGE_BYTES); CP_COMMIT(); }
    int stg = 0;
    for (int ch = 0; ch < nch; ch++) {
        if (ch + 1 < nch) CP_WAIT(1); else CP_WAIT(0);
        __syncthreads();
        const uint32_t Ab = sb + stg * STAGE_BYTES;
        const uint32_t Bb = Ab + 16384;
        const bool pre = (ch + 2 < nch);
        int s2 = stg + 2; if (s2 >= 3) s2 -= 3;
        const uint32_t s2b = sb + s2 * STAGE_BYTES;
        if (pre) issueA(s2b);
        computeKs(Ab, Bb, 0);
        if (pre) { issueB(s2b); CP_COMMIT(); }
        computeKs(Ab, Bb, 1);
        if (++stg == 3) stg = 0;
    }

    // ---- epilogue ----
    if (OUTK == 0) {
#pragma unroll
        for (int mf = 0; mf < 4; mf++) {
            const int m = m0 + warpM * 64 + mf * 16 + g4;
            const float bv0 = BIAS ? bias[m] : 0.f;
            const float bv1 = BIAS ? bias[m + 8] : 0.f;
#pragma unroll
            for (int nf = 0; nf < 4; nf++) {
                const int n = n0 + warpN * 32 + nf * 8 + 2 * tig;
                *(float2*)(Cf + (size_t)m * ldc + n) =
                    make_float2(acc[mf][nf][0] + bv0, acc[mf][nf][1] + bv0);
                *(float2*)(Cf + (size_t)(m + 8) * ldc + n) =
                    make_float2(acc[mf][nf][2] + bv1, acc[mf][nf][3] + bv1);
            }
        }
    } else if (FUSED3 && opsel == 2) {
#pragma unroll
        for (int mf = 0; mf < 4; mf++) {
            const int m = m0 + warpM * 64 + mf * 16 + g4;
            const float bv0 = BIAS ? bias[m] : 0.f;
            const float bv1 = BIAS ? bias[m + 8] : 0.f;
#pragma unroll
            for (int nf = 0; nf < 4; nf++) {
                const int n = n0 + warpN * 32 + nf * 8 + 2 * tig;
                uint32_t h01, l01, h23, l23;
                split2(acc[mf][nf][0] + bv0, acc[mf][nf][1] + bv0, h01, l01);
                split2(acc[mf][nf][2] + bv1, acc[mf][nf][3] + bv1, h23, l23);
                *(uint32_t*)((unsigned short*)Chg + (size_t)m * ldc + n) = h01;
                *(uint32_t*)((unsigned short*)Clg + (size_t)m * ldc + n) = l01;
                *(uint32_t*)((unsigned short*)Chg + (size_t)(m + 8) * ldc + n) = h23;
                *(uint32_t*)((unsigned short*)Clg + (size_t)(m + 8) * ldc + n) = l23;
            }
        }
    } else {
        __syncthreads();
        float* stgm = (float*)smem;                 // [128 n][stride 130]
#pragma unroll
        for (int mf = 0; mf < 4; mf++) {
            const int ml = warpM * 64 + mf * 16 + g4;
            const float bv0 = BIAS ? bias[m0 + ml] : 0.f;
            const float bv1 = BIAS ? bias[m0 + ml + 8] : 0.f;
#pragma unroll
            for (int nf = 0; nf < 4; nf++) {
                const int nl = warpN * 32 + nf * 8 + 2 * tig;
                stgm[nl * 130 + ml]           = acc[mf][nf][0] + bv0;
                stgm[(nl + 1) * 130 + ml]     = acc[mf][nf][1] + bv0;
                stgm[nl * 130 + ml + 8]       = acc[mf][nf][2] + bv1;
                stgm[(nl + 1) * 130 + ml + 8] = acc[mf][nf][3] + bv1;
            }
        }
        __syncthreads();
#pragma unroll
        for (int j = 0; j < 8; j++) {
            const int e = tid + j * 256;
            const int row = e >> 4, seg = e & 15;
            const float* src = stgm + row * 130 + seg * 8;
            uint32_t h[4], l[4];
            split2(src[0], src[1], h[0], l[0]);
            split2(src[2], src[3], h[1], l[1]);
            split2(src[4], src[5], h[2], l[2]);
            split2(src[6], src[7], h[3], l[3]);
            const size_t off = (size_t)(n0 + row) * ldc + m0 + seg * 8;
            *(uint4*)((unsigned short*)Chg + off) = make_uint4(h[0], h[1], h[2], h[3]);
            *(uint4*)((unsigned short*)Clg + off) = make_uint4(l[0], l[1], l[2], l[3]);
        }
    }
}

// ---------------- fp32 -> bf16 hi/lo plane splits -----------------------------
__global__ __launch_bounds__(256) void split_kernel(
    const float4* __restrict__ src, uint2* __restrict__ hi, uint2* __restrict__ lo, int n4)
{
    const int i = blockIdx.x * 256 + threadIdx.x;
    if (i >= n4) return;
    const float4 v = src[i];
    uint32_t h0, l0, h1, l1;
    split2(v.x, v.y, h0, l0);
    split2(v.z, v.w, h1, l1);
    hi[i] = make_uint2(h0, h1);
    lo[i] = make_uint2(l0, l1);
}

// 4 weight tensors in one launch (blockIdx.y selects tensor)
__global__ __launch_bounds__(256) void split4_kernel(
    const float4* s0, uint2* h0, uint2* l0,
    const float4* s1, uint2* h1, uint2* l1,
    const float4* s2p, uint2* h2, uint2* l2,
    const float4* s3, uint2* h3, uint2* l3, int n4)
{
    const float4* s; uint2 *hh, *ll;
    switch (blockIdx.y) {
        case 0: s = s0;  hh = h0; ll = l0; break;
        case 1: s = s1;  hh = h1; ll = l1; break;
        case 2: s = s2p; hh = h2; ll = l2; break;
        default: s = s3; hh = h3; ll = l3; break;
    }
    const int i = blockIdx.x * 256 + threadIdx.x;
    if (i >= n4) return;
    const float4 v = s[i];
    uint32_t a0, b0, a1, b1;
    split2(v.x, v.y, a0, b0);
    split2(v.z, v.w, a1, b1);
    hh[i] = make_uint2(a0, a1);
    ll[i] = make_uint2(b0, b1);
}

// ---------------- softmax: W fp32 rows -> P bf16 hi/lo planes ----------------
__global__ __launch_bounds__(256) void softmax_kernel(
    const float* __restrict__ W, bf16* __restrict__ Ph, bf16* __restrict__ Pl)
{
    const float4* p4 = (const float4*)(W + (size_t)blockIdx.x * NT);
    const int t = threadIdx.x;
    float4 a = p4[t], b = p4[t + 256];
    float x[8] = {a.x, a.y, a.z, a.w, b.x, b.y, b.z, b.w};

    float m = x[0];
#pragma unroll
    for (int r = 1; r < 8; r++) m = fmaxf(m, x[r]);
#pragma unroll
    for (int o = 16; o; o >>= 1) m = fmaxf(m, __shfl_xor_sync(0xffffffffu, m, o));
    __shared__ float smax[8], ssum[8];
    if ((t & 31) == 0) smax[t >> 5] = m;
    __syncthreads();
    m = smax[0];
#pragma unroll
    for (int i = 1; i < 8; i++) m = fmaxf(m, smax[i]);
    float e[8], s = 0.f;
#pragma unroll
    for (int r = 0; r < 8; r++) { e[r] = __expf(x[r] - m); s += e[r]; }
#pragma unroll
    for (int o = 16; o; o >>= 1) s += __shfl_xor_sync(0xffffffffu, s, o);
    if ((t & 31) == 0) ssum[t >> 5] = s;
    __syncthreads();
    s = ssum[0];
#pragma unroll
    for (int i = 1; i < 8; i++) s += ssum[i];
    const float inv = 1.f / s;

    uint2* ph2 = (uint2*)(Ph + (size_t)blockIdx.x * NT);
    uint2* pl2 = (uint2*)(Pl + (size_t)blockIdx.x * NT);
    uint32_t h0, l0, h1, l1;
    split2(e[0] * inv, e[1] * inv, h0, l0);
    split2(e[2] * inv, e[3] * inv, h1, l1);
    ph2[t] = make_uint2(h0, h1);
    pl2[t] = make_uint2(l0, l1);
    split2(e[4] * inv, e[5] * inv, h0, l0);
    split2(e[6] * inv, e[7] * inv, h1, l1);
    ph2[t + 256] = make_uint2(h0, h1);
    pl2[t + 256] = make_uint2(l0, l1);
}

// ---------------- BatchNorm stats + apply (vectorized) -----------------------
__global__ __launch_bounds__(256) void bn_stats_kernel(
    const float4* __restrict__ h4, float* __restrict__ mean, float* __restrict__ istd)
{
    const int c = blockIdx.x;
    float s1 = 0.f, s2 = 0.f;
    for (int i = threadIdx.x; i < NB * NT / 4; i += 256) {
        const int b = i >> 9, t4 = i & 511;
        const float4 v = h4[(size_t)b * (NC * NT / 4) + (size_t)c * (NT / 4) + t4];
        s1 += v.x + v.y + v.z + v.w;
        s2 += v.x * v.x + v.y * v.y + v.z * v.z + v.w * v.w;
    }
#pragma unroll
    for (int o = 16; o; o >>= 1) {
        s1 += __shfl_xor_sync(0xffffffffu, s1, o);
        s2 += __shfl_xor_sync(0xffffffffu, s2, o);
    }
    __shared__ float a1[8], a2[8];
    if ((threadIdx.x & 31) == 0) { a1[threadIdx.x >> 5] = s1; a2[threadIdx.x >> 5] = s2; }
    __syncthreads();
    if (threadIdx.x == 0) {
        float t1 = 0.f, t2 = 0.f;
#pragma unroll
        for (int i = 0; i < 8; i++) { t1 += a1[i]; t2 += a2[i]; }
        const float n = (float)(NB * NT);
        const float mu = t1 / n;
        const float var = t2 / n - mu * mu;
        mean[c] = mu;
        istd[c] = rsqrtf(var + 1e-5f);
    }
}

__global__ __launch_bounds__(256) void bn_apply_kernel(
    const float4* __restrict__ inpt, const float4* __restrict__ h,
    const float* __restrict__ gamma, const float* __restrict__ beta,
    const float* __restrict__ mean, const float* __restrict__ istd,
    float4* __restrict__ out)
{
    const int i = blockIdx.x * 256 + threadIdx.x;     // NB*NC*NT/4 elems
    const int c = (i >> 9) & (NC - 1);
    const float gm = gamma[c] * istd[c];
    const float bt = beta[c] - mean[c] * gm;
    const float4 iv = inpt[i], hv = h[i];
    out[i] = make_float4(iv.x + gm * hv.x + bt, iv.y + gm * hv.y + bt,
                         iv.z + gm * hv.z + bt, iv.w + gm * hv.w + bt);
}

// ---------------- launch -----------------------------------------------------
extern "C" void kernel_launch(void* const* d_in, const int* in_sizes, int n_in,
                              void* d_out, int out_size)
{
    const float* inpt    = (const float*)d_in[0];
    const float* theta_w = (const float*)d_in[1];
    const float* theta_b = (const float*)d_in[2];
    const float* phi_w   = (const float*)d_in[3];
    const float* phi_b   = (const float*)d_in[4];
    const float* gw      = (const float*)d_in[5];
    const float* gb      = (const float*)d_in[6];
    const float* ht_w    = (const float*)d_in[7];
    const float* ht_b    = (const float*)d_in[8];
    const float* bn_g    = (const float*)d_in[9];
    const float* bn_b    = (const float*)d_in[10];
    float* out = (float*)d_out;

    float *p_W, *p_h, *p_mean, *p_istd;
    bf16 *p_Ph, *p_Pl, *p_thTh, *p_thTl, *p_phTh, *p_phTl, *p_gh, *p_gl, *p_atTh, *p_atTl;
    bf16 *p_inh, *p_inl, *p_twh, *p_twl, *p_pwh, *p_pwl, *p_gwh, *p_gwl, *p_hwh, *p_hwl;
    cudaGetSymbolAddress((void**)&p_W,    g_W);
    cudaGetSymbolAddress((void**)&p_h,    g_h);
    cudaGetSymbolAddress((void**)&p_mean, g_mean);
    cudaGetSymbolAddress((void**)&p_istd, g_istd);
    cudaGetSymbolAddress((void**)&p_Ph,   g_Ph);   cudaGetSymbolAddress((void**)&p_Pl,   g_Pl);
    cudaGetSymbolAddress((void**)&p_thTh, g_thTh); cudaGetSymbolAddress((void**)&p_thTl, g_thTl);
    cudaGetSymbolAddress((void**)&p_phTh, g_phTh); cudaGetSymbolAddress((void**)&p_phTl, g_phTl);
    cudaGetSymbolAddress((void**)&p_gh,   g_gh);   cudaGetSymbolAddress((void**)&p_gl,   g_gl);
    cudaGetSymbolAddress((void**)&p_atTh, g_atTh); cudaGetSymbolAddress((void**)&p_atTl, g_atTl);
    cudaGetSymbolAddress((void**)&p_inh,  g_inh);  cudaGetSymbolAddress((void**)&p_inl,  g_inl);
    cudaGetSymbolAddress((void**)&p_twh,  g_twh);  cudaGetSymbolAddress((void**)&p_twl,  g_twl);
    cudaGetSymbolAddress((void**)&p_pwh,  g_pwh);  cudaGetSymbolAddress((void**)&p_pwl,  g_pwl);
    cudaGetSymbolAddress((void**)&p_gwh,  g_gwh);  cudaGetSymbolAddress((void**)&p_gwl,  g_gwl);
    cudaGetSymbolAddress((void**)&p_hwh,  g_hwh);  cudaGetSymbolAddress((void**)&p_hwl,  g_hwl);

    cudaFuncSetAttribute(tgemm<true,  true,  true,  2>, cudaFuncAttributeMaxDynamicSharedMemorySize, SMEM_BYTES);
    cudaFuncSetAttribute(tgemm<false, false, false, 0>, cudaFuncAttributeMaxDynamicSharedMemorySize, SMEM_BYTES);
    cudaFuncSetAttribute(tgemm<true,  false, false, 2>, cudaFuncAttributeMaxDynamicSharedMemorySize, SMEM_BYTES);
    cudaFuncSetAttribute(tgemm<false, true,  false, 0>, cudaFuncAttributeMaxDynamicSharedMemorySize, SMEM_BYTES);

    const long long sTD = (long long)NT * ND;
    const long long sDT = (long long)ND * NT;
    const long long sCT = (long long)NC * NT;
    const long long sTT = (long long)NT * NT;

    // 0) pre-split inpt (1 launch) + the four weight matrices (1 launch)
    split_kernel<<<(NB * NC * NT / 4 + 255) / 256, 256>>>(
        (const float4*)inpt, (uint2*)p_inh, (uint2*)p_inl, NB * NC * NT / 4);
    {
        dim3 grid((ND * NC / 4 + 255) / 256, 4);
        split4_kernel<<<grid, 256>>>(
            (const float4*)theta_w, (uint2*)p_twh, (uint2*)p_twl,
            (const float4*)phi_w,   (uint2*)p_pwh, (uint2*)p_pwl,
            (const float4*)gw,      (uint2*)p_gwh, (uint2*)p_gwl,
            (const float4*)ht_w,    (uint2*)p_hwh, (uint2*)p_hwl,
            ND * NC / 4);
    }

    // 1) fused theta/phi/g: M=D, N=T, K=C; B = inpt planes (TB); 768 CTAs
    {
        dim3 grid(NT / 128, ND / 128, 3 * NB);
        tgemm<true, true, true, 2><<<grid, 256, SMEM_BYTES>>>(
            p_twh, p_twl, p_inh, p_inl, nullptr, p_thTh, p_thTl, theta_b,
            p_pwh, p_pwl, p_phTh, p_phTl, phi_b,
            p_gwh, p_gwl, p_gh, p_gl, gb,
            NC, NC, NT, ND, 0LL, sCT, sTD);
    }

    // 2) W = thT x phT^T : M=N=T, K=D; both natural planes; OUT fp32 (T,S)
    {
        dim3 grid(NT / 128, NT / 128, NB);
        tgemm<false, false, false, 0><<<grid, 256, SMEM_BYTES>>>(
            p_thTh, p_thTl, p_phTh, p_phTl, p_W, nullptr, nullptr, nullptr,
            nullptr, nullptr, nullptr, nullptr, nullptr,
            nullptr, nullptr, nullptr, nullptr, nullptr,
            ND, ND, ND, NT, sTD, sTD, sTT);
    }

    // 3) softmax rows of W -> P planes
    softmax_kernel<<<NB * NT, 256>>>(p_W, p_Ph, p_Pl);

    // 4) attn^T = (g x P)^T : M=D, N=S, K=T; B = P planes (TB); OUT staged planes (S,D)
    {
        dim3 grid(NT / 128, ND / 128, NB);
        tgemm<true, false, false, 2><<<grid, 256, SMEM_BYTES>>>(
            p_gh, p_gl, p_Ph, p_Pl, nullptr, p_atTh, p_atTl, nullptr,
            nullptr, nullptr, nullptr, nullptr, nullptr,
            nullptr, nullptr, nullptr, nullptr, nullptr,
            NT, NT, NT, ND, sDT, sTT, sTD);
    }

    // 5) h = ht_w x attn : M=C, N=T, K=D; B = attn^T planes natural; OUT fp32 (C,T)
    {
        dim3 grid(NT / 128, NC / 128, NB);
        tgemm<false, true, false, 0><<<grid, 256, SMEM_BYTES>>>(
            p_hwh, p_hwl, p_atTh, p_atTl, p_h, nullptr, nullptr, ht_b,
            nullptr, nullptr, nullptr, nullptr, nullptr,
            nullptr, nullptr, nullptr, nullptr, nullptr,
            ND, ND, ND, NT, 0LL, sTD, sCT);
    }

    // 6) BN stats + apply with residual
    bn_stats_kernel<<<NC, 256>>>((const float4*)p_h, p_mean, p_istd);
    bn_apply_kernel<<<(NB * NC * NT / 4) / 256, 256>>>(
        (const float4*)inpt, (const float4*)p_h, bn_g, bn_b,
        p_mean, p_istd, (float4*)out);
}

// round 17
// speedup vs baseline: 1.6614x; 1.0181x over previous
#include <cuda_runtime.h>
#include <cuda_bf16.h>
#include <cstdint>
#include <math.h>

#define NB 8
#define NC 512
#define ND 256
#define NT 2048

typedef __nv_bfloat16 bf16;

// ---------------- scratch (device globals; no allocations allowed) ----------
__device__ float g_W[(size_t)NB * NT * NT];      // W fp32 (B,T,S)
__device__ float g_h[(size_t)NB * NC * NT];      // h fp32 (B,C,T)
__device__ bf16 g_Ph[(size_t)NB * NT * NT], g_Pl[(size_t)NB * NT * NT];     // P planes
__device__ bf16 g_thTh[(size_t)NB * NT * ND], g_thTl[(size_t)NB * NT * ND]; // theta^T (T,D)
__device__ bf16 g_phTh[(size_t)NB * NT * ND], g_phTl[(size_t)NB * NT * ND]; // phi^T   (T,D)
__device__ bf16 g_gh  [(size_t)NB * ND * NT], g_gl  [(size_t)NB * ND * NT]; // g       (D,T)
__device__ bf16 g_atTh[(size_t)NB * NT * ND], g_atTl[(size_t)NB * NT * ND]; // attn^T  (S,D)
__device__ bf16 g_inh [(size_t)NB * NC * NT], g_inl [(size_t)NB * NC * NT]; // inpt    (C,T)
__device__ bf16 g_twh[ND * NC], g_twl[ND * NC];
__device__ bf16 g_pwh[ND * NC], g_pwl[ND * NC];
__device__ bf16 g_gwh[ND * NC], g_gwl[ND * NC];
__device__ bf16 g_hwh[NC * ND], g_hwl[NC * ND];
__device__ float g_mean[NC];
__device__ float g_istd[NC];

// ---------------- helpers ----------------------------------------------------
__device__ __forceinline__ uint32_t smem_u32(const void* p) {
    uint32_t a;
    asm("{ .reg .u64 t; cvta.to.shared.u64 t, %1; cvt.u32.u64 %0, t; }" : "=r"(a) : "l"(p));
    return a;
}
__device__ __forceinline__ void split2(float x, float y, uint32_t& hi, uint32_t& lo) {
    __nv_bfloat162 h = __floats2bfloat162_rn(x, y);
    float hx = __low2float(h), hy = __high2float(h);
    __nv_bfloat162 l = __floats2bfloat162_rn(x - hx, y - hy);
    hi = *reinterpret_cast<uint32_t*>(&h);
    lo = *reinterpret_cast<uint32_t*>(&l);
}
__device__ __forceinline__ void mma16(float* d, const uint32_t* a, const uint32_t* b) {
    asm volatile(
        "mma.sync.aligned.m16n8k16.row.col.f32.bf16.bf16.f32 "
        "{%0,%1,%2,%3}, {%4,%5,%6,%7}, {%8,%9}, {%0,%1,%2,%3};"
        : "+f"(d[0]), "+f"(d[1]), "+f"(d[2]), "+f"(d[3])
        : "r"(a[0]), "r"(a[1]), "r"(a[2]), "r"(a[3]), "r"(b[0]), "r"(b[1]));
}
#define CP16(dst, src) \
    asm volatile("cp.async.cg.shared.global [%0], [%1], 16;" :: "r"(dst), "l"(src) : "memory")
#define CP_COMMIT() asm volatile("cp.async.commit_group;" ::: "memory")
#define CP_WAIT(n)  asm volatile("cp.async.wait_group %0;" :: "n"(n) : "memory")
#define LDSM_X4(R, addr) \
    asm volatile("ldmatrix.sync.aligned.m8n8.x4.shared.b16 {%0,%1,%2,%3}, [%4];" \
        : "=r"((R)[0]), "=r"((R)[1]), "=r"((R)[2]), "=r"((R)[3]) : "r"(addr))
#define LDSM_X4T(R, addr) \
    asm volatile("ldmatrix.sync.aligned.m8n8.x4.trans.shared.b16 {%0,%1,%2,%3}, [%4];" \
        : "=r"((R)[0]), "=r"((R)[1]), "=r"((R)[2]), "=r"((R)[3]) : "r"(addr))

// SMEM: 3 stages x 32KB. Stage: A 16KB, B 16KB (B region at stage base + 16384).
#define STAGE_BYTES 32768
static constexpr int SMEM_BYTES = 3 * STAGE_BYTES;   // 98304

// ---------------- bf16x3 GEMM: cp.async + ldmatrix, 3-stage pipeline ---------
// All operands bf16 hi/lo planes. A natural (M,K) lda.
// TB=false: B natural (N,K) ldb. TB=true: B (K,N) ldb.
// OUTK=0: C fp32 natural (M,N) ldc. OUTK=2: C planes transposed via smem stage.
// FUSED3: bz = op*NB+b; op 0,1 -> staged planes (ldc=ND); op 2 -> natural planes (ldc=NT).
template <bool TB, bool BIAS, bool FUSED3, int OUTK>
__global__ __launch_bounds__(256, 2) void tgemm(
    const bf16* __restrict__ Ahi, const bf16* __restrict__ Alo,
    const bf16* __restrict__ Bhi, const bf16* __restrict__ Blo,
    float* __restrict__ Cf, bf16* __restrict__ Chg, bf16* __restrict__ Clg,
    const float* __restrict__ bias,
    const bf16* A1hi, const bf16* A1lo, bf16* C1hg, bf16* C1lg, const float* bias1,
    const bf16* A2hi, const bf16* A2lo, bf16* C2hg, bf16* C2lg, const float* bias2,
    int K, int lda, int ldb, int ldc, long long sA, long long sB, long long sC)
{
    extern __shared__ char smem[];
    const uint32_t sb = smem_u32(smem);
    const int tid = threadIdx.x;
    const int lane = tid & 31;
    const int wid = tid >> 5;
    const int warpM = wid >> 2, warpN = wid & 3;
    const int g4 = lane >> 2, tig = lane & 3;
    const int sub = lane >> 3, l7 = lane & 7;

    int bz = blockIdx.z;
    int opsel = 0;
    if (FUSED3) {
        opsel = bz >> 3;
        bz &= 7;
        if (opsel == 1) { Ahi = A1hi; Alo = A1lo; Chg = C1hg; Clg = C1lg; bias = bias1; }
        else if (opsel == 2) { Ahi = A2hi; Alo = A2lo; Chg = C2hg; Clg = C2lg; bias = bias2; ldc = NT; }
    }
    const int m0 = blockIdx.y * 128, n0 = blockIdx.x * 128;
    Ahi += (long long)bz * sA;  Alo += (long long)bz * sA;
    Bhi += (long long)bz * sB;  Blo += (long long)bz * sB;
    if (OUTK == 0) Cf += (long long)bz * sC;
    else { Chg += (long long)bz * sC; Clg += (long long)bz * sC; }

    float acc[4][4][4];
#pragma unroll
    for (int a = 0; a < 4; a++)
#pragma unroll
        for (int b = 0; b < 4; b++)
#pragma unroll
            for (int c = 0; c < 4; c++) acc[a][b][c] = 0.f;

    const int nch = K >> 5;

    // ---- de-phase co-resident CTAs (placement is contiguous-modular; the two
    // CTAs sharing an SM are one 148-wave apart). Timing-only: no numeric effect.
    {
        const int bidlin = (blockIdx.z * gridDim.y + blockIdx.y) * gridDim.x + blockIdx.x;
        if ((bidlin / 148) & 1) __nanosleep(1000);
    }

    // ---- hoisted per-thread addressing (linear in j and chunk) ----
    const int rowA = tid >> 3, c8 = tid & 7;
    const bf16* srcA = (c8 < 4 ? Ahi : Alo) + (size_t)(m0 + rowA) * lda + (c8 & 3) * 8;
    const uint32_t dstA0 = rowA * 128 + ((c8 * 16) ^ ((rowA & 7) << 4));
    const int ldaJ = 32 * lda;                       // A j-step (elems)

    const bf16* srcB;
    uint32_t dstB0;                                   // includes +16384 B-region offset
    int ldbJ, ldbC;                                   // B j-step / chunk-step (elems)
    if (TB) {
        const int kr = tid >> 5, c = tid & 31, pl = c >> 4, c16 = c & 15;
        srcB = (pl ? Blo : Bhi) + (size_t)kr * ldb + n0 + c16 * 8;
        dstB0 = 16384 + pl * 8192 + kr * 256 + ((c16 * 16) ^ ((kr & 7) << 4));
        ldbJ = 8 * ldb; ldbC = 32 * ldb;
    } else {
        srcB = (c8 < 4 ? Bhi : Blo) + (size_t)(n0 + rowA) * ldb + (c8 & 3) * 8;
        dstB0 = 16384 + dstA0;
        ldbJ = 32 * ldb; ldbC = 32;
    }

    auto issueA = [&](uint32_t base) {
#pragma unroll
        for (int j = 0; j < 4; j++)
            CP16(base + dstA0 + j * 4096, srcA + (size_t)j * ldaJ);
        srcA += 32;
    };
    auto issueB = [&](uint32_t base) {
        const int jstride = TB ? 2048 : 4096;
#pragma unroll
        for (int j = 0; j < 4; j++)
            CP16(base + dstB0 + j * jstride, srcB + (size_t)j * ldbJ);
        srcB += ldbC;
    };

    auto ldAfrag = [&](uint32_t Ab, int ks, int plane, int mf, uint32_t* R) {
        const int r = warpM * 64 + mf * 16 + l7 + ((sub & 1) << 3);
        const int kb = plane * 64 + ks * 32 + ((sub >> 1) << 4);
        LDSM_X4(R, Ab + r * 128 + (kb ^ ((r & 7) << 4)));
    };
    auto ldBfrag = [&](uint32_t Bb, int ks, int plane, int pair, uint32_t* R) {
        if (TB) {
            const int kr = ks * 16 + ((sub & 1) << 3) + l7;
            const int nb = (warpN * 32 + pair * 16 + ((sub >> 1) << 3)) * 2;
            LDSM_X4T(R, Bb + plane * 8192 + kr * 256 + (nb ^ ((kr & 7) << 4)));
        } else {
            const int n = warpN * 32 + pair * 16 + ((sub >> 1) << 3) + l7;
            const int kb = plane * 64 + ks * 32 + ((sub & 1) << 4);
            LDSM_X4(R, Bb + n * 128 + (kb ^ ((n & 7) << 4)));
        }
    };

    // compute one k-step: all shared-independent LDSMs up front, then
    // term1 (hiA*hiB) -> term3 (hiA*loB) -> term2 (loA*hiB, transient A-lo).
    auto computeKs = [&](uint32_t Ab, uint32_t Bb, int ks) {
        uint32_t afh[4][4];
        uint32_t bfh[2][4], bfl[2][4];
#pragma unroll
        for (int mf = 0; mf < 4; mf++) ldAfrag(Ab, ks, 0, mf, afh[mf]);
        ldBfrag(Bb, ks, 0, 0, bfh[0]);
        ldBfrag(Bb, ks, 0, 1, bfh[1]);
        ldBfrag(Bb, ks, 1, 0, bfl[0]);
        ldBfrag(Bb, ks, 1, 1, bfl[1]);
        // term 1: hiA * hiB
#pragma unroll
        for (int mf = 0; mf < 4; mf++)
#pragma unroll
            for (int nf = 0; nf < 4; nf++)
                mma16(acc[mf][nf], afh[mf], &bfh[nf >> 1][(nf & 1) * 2]);
        // term 3: hiA * loB
#pragma unroll
        for (int mf = 0; mf < 4; mf++)
#pragma unroll
            for (int nf = 0; nf < 4; nf++)
                mma16(acc[mf][nf], afh[mf], &bfl[nf >> 1][(nf & 1) * 2]);
        // term 2: loA * hiB (A-lo fragments transient)
#pragma unroll
        for (int mf = 0; mf < 4; mf++) {
            uint32_t t[4];
            ldAfrag(Ab, ks, 1, mf, t);
#pragma unroll
            for (int nf = 0; nf < 4; nf++)
                mma16(acc[mf][nf], t, &bfh[nf >> 1][(nf & 1) * 2]);
        }
    };

    // ---- pipeline: prefetch distance 2; prefetch interleaved into compute ----
    issueA(sb); issueB(sb); CP_COMMIT();
    if (nch > 1) { issueA(sb + STAGE_BYTES); issueB(sb + STAGE_BYTES); CP_COMMIT(); }
    int stg = 0;
    for (int ch = 0; ch < nch; ch++) {
        if (ch + 1 < nch) CP_WAIT(1); else CP_WAIT(0);
        __syncthreads();
        const uint32_t Ab = sb + stg * STAGE_BYTES;
        const uint32_t Bb = Ab + 16384;
        const bool pre = (ch + 2 < nch);
        int s2 = stg + 2; if (s2 >= 3) s2 -= 3;
        const uint32_t s2b = sb + s2 * STAGE_BYTES;
        if (pre) issueA(s2b);
        computeKs(Ab, Bb, 0);
        if (pre) { issueB(s2b); CP_COMMIT(); }
        computeKs(Ab, Bb, 1);
        if (++stg == 3) stg = 0;
    }

    // ---- epilogue ----
    if (OUTK == 0) {
#pragma unroll
        for (int mf = 0; mf < 4; mf++) {
            const int m = m0 + warpM * 64 + mf * 16 + g4;
            const float bv0 = BIAS ? bias[m] : 0.f;
            const float bv1 = BIAS ? bias[m + 8] : 0.f;
#pragma unroll
            for (int nf = 0; nf < 4; nf++) {
                const int n = n0 + warpN * 32 + nf * 8 + 2 * tig;
                *(float2*)(Cf + (size_t)m * ldc + n) =
                    make_float2(acc[mf][nf][0] + bv0, acc[mf][nf][1] + bv0);
                *(float2*)(Cf + (size_t)(m + 8) * ldc + n) =
                    make_float2(acc[mf][nf][2] + bv1, acc[mf][nf][3] + bv1);
            }
        }
    } else if (FUSED3 && opsel == 2) {
#pragma unroll
        for (int mf = 0; mf < 4; mf++) {
            const int m = m0 + warpM * 64 + mf * 16 + g4;
            const float bv0 = BIAS ? bias[m] : 0.f;
            const float bv1 = BIAS ? bias[m + 8] : 0.f;
#pragma unroll
            for (int nf = 0; nf < 4; nf++) {
                const int n = n0 + warpN * 32 + nf * 8 + 2 * tig;
                uint32_t h01, l01, h23, l23;
                split2(acc[mf][nf][0] + bv0, acc[mf][nf][1] + bv0, h01, l01);
                split2(acc[mf][nf][2] + bv1, acc[mf][nf][3] + bv1, h23, l23);
                *(uint32_t*)((unsigned short*)Chg + (size_t)m * ldc + n) = h01;
                *(uint32_t*)((unsigned short*)Clg + (size_t)m * ldc + n) = l01;
                *(uint32_t*)((unsigned short*)Chg + (size_t)(m + 8) * ldc + n) = h23;
                *(uint32_t*)((unsigned short*)Clg + (size_t)(m + 8) * ldc + n) = l23;
            }
        }
    } else {
        __syncthreads();
        float* stgm = (float*)smem;                 // [128 n][stride 130]
#pragma unroll
        for (int mf = 0; mf < 4; mf++) {
            const int ml = warpM * 64 + mf * 16 + g4;
            const float bv0 = BIAS ? bias[m0 + ml] : 0.f;
            const float bv1 = BIAS ? bias[m0 + ml + 8] : 0.f;
#pragma unroll
            for (int nf = 0; nf < 4; nf++) {
                const int nl = warpN * 32 + nf * 8 + 2 * tig;
                stgm[nl * 130 + ml]           = acc[mf][nf][0] + bv0;
                stgm[(nl + 1) * 130 + ml]     = acc[mf][nf][1] + bv0;
                stgm[nl * 130 + ml + 8]       = acc[mf][nf][2] + bv1;
                stgm[(nl + 1) * 130 + ml + 8] = acc[mf][nf][3] + bv1;
            }
        }
        __syncthreads();
#pragma unroll
        for (int j = 0; j < 8; j++) {
            const int e = tid + j * 256;
            const int row = e >> 4, seg = e & 15;
            const float* src = stgm + row * 130 + seg * 8;
            uint32_t h[4], l[4];
            split2(src[0], src[1], h[0], l[0]);
            split2(src[2], src[3], h[1], l[1]);
            split2(src[4], src[5], h[2], l[2]);
            split2(src[6], src[7], h[3], l[3]);
            const size_t off = (size_t)(n0 + row) * ldc + m0 + seg * 8;
            *(uint4*)((unsigned short*)Chg + off) = make_uint4(h[0], h[1], h[2], h[3]);
            *(uint4*)((unsigned short*)Clg + off) = make_uint4(l[0], l[1], l[2], l[3]);
        }
    }
}

// ---------------- fp32 -> bf16 hi/lo plane splits -----------------------------
__global__ __launch_bounds__(256) void split_kernel(
    const float4* __restrict__ src, uint2* __restrict__ hi, uint2* __restrict__ lo, int n4)
{
    const int i = blockIdx.x * 256 + threadIdx.x;
    if (i >= n4) return;
    const float4 v = src[i];
    uint32_t h0, l0, h1, l1;
    split2(v.x, v.y, h0, l0);
    split2(v.z, v.w, h1, l1);
    hi[i] = make_uint2(h0, h1);
    lo[i] = make_uint2(l0, l1);
}

// 4 weight tensors in one launch (blockIdx.y selects tensor)
__global__ __launch_bounds__(256) void split4_kernel(
    const float4* s0, uint2* h0, uint2* l0,
    const float4* s1, uint2* h1, uint2* l1,
    const float4* s2p, uint2* h2, uint2* l2,
    const float4* s3, uint2* h3, uint2* l3, int n4)
{
    const float4* s; uint2 *hh, *ll;
    switch (blockIdx.y) {
        case 0: s = s0;  hh = h0; ll = l0; break;
        case 1: s = s1;  hh = h1; ll = l1; break;
        case 2: s = s2p; hh = h2; ll = l2; break;
        default: s = s3; hh = h3; ll = l3; break;
    }
    const int i = blockIdx.x * 256 + threadIdx.x;
    if (i >= n4) return;
    const float4 v = s[i];
    uint32_t a0, b0, a1, b1;
    split2(v.x, v.y, a0, b0);
    split2(v.z, v.w, a1, b1);
    hh[i] = make_uint2(a0, a1);
    ll[i] = make_uint2(b0, b1);
}

// ---------------- softmax: W fp32 rows -> P bf16 hi/lo planes ----------------
__global__ __launch_bounds__(256) void softmax_kernel(
    const float* __restrict__ W, bf16* __restrict__ Ph, bf16* __restrict__ Pl)
{
    const float4* p4 = (const float4*)(W + (size_t)blockIdx.x * NT);
    const int t = threadIdx.x;
    float4 a = p4[t], b = p4[t + 256];
    float x[8] = {a.x, a.y, a.z, a.w, b.x, b.y, b.z, b.w};

    float m = x[0];
#pragma unroll
    for (int r = 1; r < 8; r++) m = fmaxf(m, x[r]);
#pragma unroll
    for (int o = 16; o; o >>= 1) m = fmaxf(m, __shfl_xor_sync(0xffffffffu, m, o));
    __shared__ float smax[8], ssum[8];
    if ((t & 31) == 0) smax[t >> 5] = m;
    __syncthreads();
    m = smax[0];
#pragma unroll
    for (int i = 1; i < 8; i++) m = fmaxf(m, smax[i]);
    float e[8], s = 0.f;
#pragma unroll
    for (int r = 0; r < 8; r++) { e[r] = __expf(x[r] - m); s += e[r]; }
#pragma unroll
    for (int o = 16; o; o >>= 1) s += __shfl_xor_sync(0xffffffffu, s, o);
    if ((t & 31) == 0) ssum[t >> 5] = s;
    __syncthreads();
    s = ssum[0];
#pragma unroll
    for (int i = 1; i < 8; i++) s += ssum[i];
    const float inv = 1.f / s;

    uint2* ph2 = (uint2*)(Ph + (size_t)blockIdx.x * NT);
    uint2* pl2 = (uint2*)(Pl + (size_t)blockIdx.x * NT);
    uint32_t h0, l0, h1, l1;
    split2(e[0] * inv, e[1] * inv, h0, l0);
    split2(e[2] * inv, e[3] * inv, h1, l1);
    ph2[t] = make_uint2(h0, h1);
    pl2[t] = make_uint2(l0, l1);
    split2(e[4] * inv, e[5] * inv, h0, l0);
    split2(e[6] * inv, e[7] * inv, h1, l1);
    ph2[t + 256] = make_uint2(h0, h1);
    pl2[t + 256] = make_uint2(l0, l1);
}

// ---------------- BatchNorm stats + apply (vectorized) -----------------------
__global__ __launch_bounds__(256) void bn_stats_kernel(
    const float4* __restrict__ h4, float* __restrict__ mean, float* __restrict__ istd)
{
    const int c = blockIdx.x;
    float s1 = 0.f, s2 = 0.f;
    for (int i = threadIdx.x; i < NB * NT / 4; i += 256) {
        const int b = i >> 9, t4 = i & 511;
        const float4 v = h4[(size_t)b * (NC * NT / 4) + (size_t)c * (NT / 4) + t4];
        s1 += v.x + v.y + v.z + v.w;
        s2 += v.x * v.x + v.y * v.y + v.z * v.z + v.w * v.w;
    }
#pragma unroll
    for (int o = 16; o; o >>= 1) {
        s1 += __shfl_xor_sync(0xffffffffu, s1, o);
        s2 += __shfl_xor_sync(0xffffffffu, s2, o);
    }
    __shared__ float a1[8], a2[8];
    if ((threadIdx.x & 31) == 0) { a1[threadIdx.x >> 5] = s1; a2[threadIdx.x >> 5] = s2; }
    __syncthreads();
    if (threadIdx.x == 0) {
        float t1 = 0.f, t2 = 0.f;
#pragma unroll
        for (int i = 0; i < 8; i++) { t1 += a1[i]; t2 += a2[i]; }
        const float n = (float)(NB * NT);
        const float mu = t1 / n;
        const float var = t2 / n - mu * mu;
        mean[c] = mu;
        istd[c] = rsqrtf(var + 1e-5f);
    }
}

__global__ __launch_bounds__(256) void bn_apply_kernel(
    const float4* __restrict__ inpt, const float4* __restrict__ h,
    const float* __restrict__ gamma, const float* __restrict__ beta,
    const float* __restrict__ mean, const float* __restrict__ istd,
    float4* __restrict__ out)
{
    const int i = blockIdx.x * 256 + threadIdx.x;     // NB*NC*NT/4 elems
    const int c = (i >> 9) & (NC - 1);
    const float gm = gamma[c] * istd[c];
    const float bt = beta[c] - mean[c] * gm;
    const float4 iv = inpt[i], hv = h[i];
    out[i] = make_float4(iv.x + gm * hv.x + bt, iv.y + gm * hv.y + bt,
                         iv.z + gm * hv.z + bt, iv.w + gm * hv.w + bt);
}

// ---------------- launch -----------------------------------------------------
extern "C" void kernel_launch(void* const* d_in, const int* in_sizes, int n_in,
                              void* d_out, int out_size)
{
    const float* inpt    = (const float*)d_in[0];
    const float* theta_w = (const float*)d_in[1];
    const float* theta_b = (const float*)d_in[2];
    const float* phi_w   = (const float*)d_in[3];
    const float* phi_b   = (const float*)d_in[4];
    const float* gw      = (const float*)d_in[5];
    const float* gb      = (const float*)d_in[6];
    const float* ht_w    = (const float*)d_in[7];
    const float* ht_b    = (const float*)d_in[8];
    const float* bn_g    = (const float*)d_in[9];
    const float* bn_b    = (const float*)d_in[10];
    float* out = (float*)d_out;

    float *p_W, *p_h, *p_mean, *p_istd;
    bf16 *p_Ph, *p_Pl, *p_thTh, *p_thTl, *p_phTh, *p_phTl, *p_gh, *p_gl, *p_atTh, *p_atTl;
    bf16 *p_inh, *p_inl, *p_twh, *p_twl, *p_pwh, *p_pwl, *p_gwh, *p_gwl, *p_hwh, *p_hwl;
    cudaGetSymbolAddress((void**)&p_W,    g_W);
    cudaGetSymbolAddress((void**)&p_h,    g_h);
    cudaGetSymbolAddress((void**)&p_mean, g_mean);
    cudaGetSymbolAddress((void**)&p_istd, g_istd);
    cudaGetSymbolAddress((void**)&p_Ph,   g_Ph);   cudaGetSymbolAddress((void**)&p_Pl,   g_Pl);
    cudaGetSymbolAddress((void**)&p_thTh, g_thTh); cudaGetSymbolAddress((void**)&p_thTl, g_thTl);
    cudaGetSymbolAddress((void**)&p_phTh, g_phTh); cudaGetSymbolAddress((void**)&p_phTl, g_phTl);
    cudaGetSymbolAddress((void**)&p_gh,   g_gh);   cudaGetSymbolAddress((void**)&p_gl,   g_gl);
    cudaGetSymbolAddress((void**)&p_atTh, g_atTh); cudaGetSymbolAddress((void**)&p_atTl, g_atTl);
    cudaGetSymbolAddress((void**)&p_inh,  g_inh);  cudaGetSymbolAddress((void**)&p_inl,  g_inl);
    cudaGetSymbolAddress((void**)&p_twh,  g_twh);  cudaGetSymbolAddress((void**)&p_twl,  g_twl);
    cudaGetSymbolAddress((void**)&p_pwh,  g_pwh);  cudaGetSymbolAddress((void**)&p_pwl,  g_pwl);
    cudaGetSymbolAddress((void**)&p_gwh,  g_gwh);  cudaGetSymbolAddress((void**)&p_gwl,  g_gwl);
    cudaGetSymbolAddress((void**)&p_hwh,  g_hwh);  cudaGetSymbolAddress((void**)&p_hwl,  g_hwl);

    cudaFuncSetAttribute(tgemm<true,  true,  true,  2>, cudaFuncAttributeMaxDynamicSharedMemorySize, SMEM_BYTES);
    cudaFuncSetAttribute(tgemm<false, false, false, 0>, cudaFuncAttributeMaxDynamicSharedMemorySize, SMEM_BYTES);
    cudaFuncSetAttribute(tgemm<true,  false, false, 2>, cudaFuncAttributeMaxDynamicSharedMemorySize, SMEM_BYTES);
    cudaFuncSetAttribute(tgemm<false, true,  false, 0>, cudaFuncAttributeMaxDynamicSharedMemorySize, SMEM_BYTES);

    const long long sTD = (long long)NT * ND;
    const long long sDT = (long long)ND * NT;
    const long long sCT = (long long)NC * NT;
    const long long sTT = (long long)NT * NT;

    // 0) pre-split inpt (1 launch) + the four weight matrices (1 launch)
    split_kernel<<<(NB * NC * NT / 4 + 255) / 256, 256>>>(
        (const float4*)inpt, (uint2*)p_inh, (uint2*)p_inl, NB * NC * NT / 4);
    {
        dim3 grid((ND * NC / 4 + 255) / 256, 4);
        split4_kernel<<<grid, 256>>>(
            (const float4*)theta_w, (uint2*)p_twh, (uint2*)p_twl,
            (const float4*)phi_w,   (uint2*)p_pwh, (uint2*)p_pwl,
            (const float4*)gw,      (uint2*)p_gwh, (uint2*)p_gwl,
            (const float4*)ht_w,    (uint2*)p_hwh, (uint2*)p_hwl,
            ND * NC / 4);
    }

    // 1) fused theta/phi/g: M=D, N=T, K=C; B = inpt planes (TB); 768 CTAs
    {
        dim3 grid(NT / 128, ND / 128, 3 * NB);
        tgemm<true, true, true, 2><<<grid, 256, SMEM_BYTES>>>(
            p_twh, p_twl, p_inh, p_inl, nullptr, p_thTh, p_thTl, theta_b,
            p_pwh, p_pwl, p_phTh, p_phTl, phi_b,
            p_gwh, p_gwl, p_gh, p_gl, gb,
            NC, NC, NT, ND, 0LL, sCT, sTD);
    }

    // 2) W = thT x phT^T : M=N=T, K=D; both natural planes; OUT fp32 (T,S)
    {
        dim3 grid(NT / 128, NT / 128, NB);
        tgemm<false, false, false, 0><<<grid, 256, SMEM_BYTES>>>(
            p_thTh, p_thTl, p_phTh, p_phTl, p_W, nullptr, nullptr, nullptr,
            nullptr, nullptr, nullptr, nullptr, nullptr,
            nullptr, nullptr, nullptr, nullptr, nullptr,
            ND, ND, ND, NT, sTD, sTD, sTT);
    }

    // 3) softmax rows of W -> P planes
    softmax_kernel<<<NB * NT, 256>>>(p_W, p_Ph, p_Pl);

    // 4) attn^T = (g x P)^T : M=D, N=S, K=T; B = P planes (TB); OUT staged planes (S,D)
    {
        dim3 grid(NT / 128, ND / 128, NB);
        tgemm<true, false, false, 2><<<grid, 256, SMEM_BYTES>>>(
            p_gh, p_gl, p_Ph, p_Pl, nullptr, p_atTh, p_atTl, nullptr,
            nullptr, nullptr, nullptr, nullptr, nullptr,
            nullptr, nullptr, nullptr, nullptr, nullptr,
            NT, NT, NT, ND, sDT, sTT, sTD);
    }

    // 5) h = ht_w x attn : M=C, N=T, K=D; B = attn^T planes natural; OUT fp32 (C,T)
    {
        dim3 grid(NT / 128, NC / 128, NB);
        tgemm<false, true, false, 0><<<grid, 256, SMEM_BYTES>>>(
            p_hwh, p_hwl, p_atTh, p_atTl, p_h, nullptr, nullptr, ht_b,
            nullptr, nullptr, nullptr, nullptr, nullptr,
            nullptr, nullptr, nullptr, nullptr, nullptr,
            ND, ND, ND, NT, 0LL, sTD, sCT);
    }

    // 6) BN stats + apply with residual
    bn_stats_kernel<<<NC, 256>>>((const float4*)p_h, p_mean, p_istd);
    bn_apply_kernel<<<(NB * NC * NT / 4) / 256, 256>>>(
        (const float4*)inpt, (const float4*)p_h, bn_g, bn_b,
        p_mean, p_istd, (float4*)out);
}